// round 1
// baseline (speedup 1.0000x reference)
#include <cuda_runtime.h>

#define Bb 4
#define Tt 2048
#define Ee 1024
#define HD 64
#define Mrows (Bb*Tt)

#define BQ 32
#define BKV 64
#define KSTRIDE 68   // K-tile row stride in floats: 272B = 17*16B -> 16B-aligned float4 rows, conflict-free phases

// scratch (no cudaMalloc allowed)
__device__ float g_q[Mrows*HD];
__device__ float g_k[Mrows*HD];
__device__ float g_v[Mrows*HD];
__device__ float g_ho[Mrows*HD];
__device__ float g_wred[Ee*HD];   // [1024][64]

// ---------------------------------------------------------------------------
// Kernel 1: QKV projections. C[m][n] = sum_k A[m][k] * W[n][k]
// M=8192, N=64, K=1024. grid (128,1,3), block 256.
// ---------------------------------------------------------------------------
__global__ void qkv_kernel(const float* __restrict__ emb,
                           const float* __restrict__ Wq,
                           const float* __restrict__ Wk,
                           const float* __restrict__ Wv) {
    __shared__ float As[64][33];
    __shared__ float Bs[64][33];
    const float* W = (blockIdx.z == 0) ? Wq : ((blockIdx.z == 1) ? Wk : Wv);
    float* outp = (blockIdx.z == 0) ? g_q : ((blockIdx.z == 1) ? g_k : g_v);
    int m0 = blockIdx.x * 64;
    int tid = threadIdx.x;
    int tx = tid & 15, ty = tid >> 4;

    float acc[4][4];
#pragma unroll
    for (int i = 0; i < 4; i++)
#pragma unroll
        for (int j = 0; j < 4; j++) acc[i][j] = 0.f;

    for (int k0 = 0; k0 < Ee; k0 += 32) {
#pragma unroll
        for (int i = 0; i < 8; i++) {
            int e = tid + i * 256;
            int mm = e >> 5, kk = e & 31;
            As[mm][kk] = emb[(size_t)(m0 + mm) * Ee + k0 + kk];
            Bs[mm][kk] = W[(size_t)mm * Ee + k0 + kk];
        }
        __syncthreads();
#pragma unroll
        for (int kk = 0; kk < 32; kk++) {
            float a[4], b[4];
#pragma unroll
            for (int i = 0; i < 4; i++) a[i] = As[ty * 4 + i][kk];
#pragma unroll
            for (int j = 0; j < 4; j++) b[j] = Bs[tx * 4 + j][kk];
#pragma unroll
            for (int i = 0; i < 4; i++)
#pragma unroll
                for (int j = 0; j < 4; j++) acc[i][j] += a[i] * b[j];
        }
        __syncthreads();
    }
#pragma unroll
    for (int i = 0; i < 4; i++)
#pragma unroll
        for (int j = 0; j < 4; j++)
            outp[(size_t)(m0 + ty * 4 + i) * HD + tx * 4 + j] = acc[i][j];
}

// ---------------------------------------------------------------------------
// Kernel 2: Wred[o][d] = sum_h W_out[o][h*64+d]   (folds tile+projection)
// ---------------------------------------------------------------------------
__global__ void wred_kernel(const float* __restrict__ Wout) {
    int idx = blockIdx.x * 256 + threadIdx.x;  // 65536 total
    int o = idx >> 6, d = idx & 63;
    float s = 0.f;
#pragma unroll
    for (int h = 0; h < 16; h++) s += Wout[(size_t)o * 1024 + h * 64 + d];
    g_wred[idx] = s;
}

// ---------------------------------------------------------------------------
// Kernel 3: causal flash attention, fp32. grid (64, 4), block 256 (8 warps).
// Each block: 32 query rows; each warp owns 4 rows; each lane owns key cols
// {lane, lane+32} for scores and dims {2*lane, 2*lane+1} for the O accumulator.
// ---------------------------------------------------------------------------
__global__ void flash_kernel() {
    extern __shared__ float sm[];
    float* Qs = sm;                          // [32][64]
    float* Ks = sm + 2048;                   // [64][KSTRIDE]
    float* Vs = sm + 2048 + 64 * KSTRIDE;    // [64][64]
    float* Ps = Vs + 4096;                   // [32][64]

    int b = blockIdx.y;
    int qt = (gridDim.x - 1) - blockIdx.x;   // heavy tiles scheduled first
    int q0 = qt * BQ;
    int tid = threadIdx.x;
    int wid = tid >> 5, lane = tid & 31;
    int r0 = wid * 4;

    const float* qbase = g_q + ((size_t)b * Tt + q0) * HD;
#pragma unroll
    for (int i = 0; i < 8; i++) {
        int e = tid + i * 256;
        Qs[e] = qbase[e];
    }

    float m[4], l[4];
    float2 o[4];
#pragma unroll
    for (int r = 0; r < 4; r++) {
        m[r] = -1e30f; l[r] = 0.f; o[r] = make_float2(0.f, 0.f);
    }

    int kmax = q0 + BQ - 1;
    int n_tiles = kmax / BKV + 1;
    __syncthreads();

    for (int t = 0; t < n_tiles; t++) {
        int k0 = t * BKV;
        const float* kb = g_k + ((size_t)b * Tt + k0) * HD;
        const float* vb = g_v + ((size_t)b * Tt + k0) * HD;
#pragma unroll
        for (int i = 0; i < 16; i++) {
            int e = tid + i * 256;
            int c = e >> 6, d = e & 63;
            Ks[c * KSTRIDE + d] = kb[e];
            Vs[e] = vb[e];
        }
        __syncthreads();

        // S = Q K^T for this warp's 4 rows x this lane's 2 key columns
        float s[4][2];
#pragma unroll
        for (int r = 0; r < 4; r++) { s[r][0] = 0.f; s[r][1] = 0.f; }
#pragma unroll
        for (int d4 = 0; d4 < 16; d4++) {
            float4 k0v = *(const float4*)(Ks + lane * KSTRIDE + d4 * 4);
            float4 k1v = *(const float4*)(Ks + (lane + 32) * KSTRIDE + d4 * 4);
#pragma unroll
            for (int r = 0; r < 4; r++) {
                float4 q = *(const float4*)(Qs + (r0 + r) * 64 + d4 * 4);
                s[r][0] += q.x * k0v.x + q.y * k0v.y + q.z * k0v.z + q.w * k0v.w;
                s[r][1] += q.x * k1v.x + q.y * k1v.y + q.z * k1v.z + q.w * k1v.w;
            }
        }

        const float scale = 0.125f;  // 1/sqrt(64)
#pragma unroll
        for (int r = 0; r < 4; r++) {
            int q_idx = q0 + r0 + r;
            float s0 = s[r][0] * scale;
            float s1 = s[r][1] * scale;
            if (k0 + lane > q_idx) s0 = -1e30f;
            if (k0 + lane + 32 > q_idx) s1 = -1e30f;
            float mx = fmaxf(s0, s1);
#pragma unroll
            for (int off = 16; off; off >>= 1)
                mx = fmaxf(mx, __shfl_xor_sync(0xffffffffu, mx, off));
            float mn = fmaxf(m[r], mx);
            float p0 = __expf(s0 - mn);
            float p1 = __expf(s1 - mn);
            float rs = p0 + p1;
#pragma unroll
            for (int off = 16; off; off >>= 1)
                rs += __shfl_xor_sync(0xffffffffu, rs, off);
            float alpha = __expf(m[r] - mn);
            m[r] = mn;
            l[r] = l[r] * alpha + rs;
            o[r].x *= alpha;
            o[r].y *= alpha;
            Ps[(r0 + r) * 64 + lane] = p0;
            Ps[(r0 + r) * 64 + lane + 32] = p1;
        }
        __syncwarp();

        // O += P V : lane owns output dims {2*lane, 2*lane+1}
        const float2* Vs2 = (const float2*)Vs;
#pragma unroll
        for (int c4 = 0; c4 < 16; c4++) {
            float2 v0 = Vs2[(c4 * 4 + 0) * 32 + lane];
            float2 v1 = Vs2[(c4 * 4 + 1) * 32 + lane];
            float2 v2 = Vs2[(c4 * 4 + 2) * 32 + lane];
            float2 v3 = Vs2[(c4 * 4 + 3) * 32 + lane];
#pragma unroll
            for (int r = 0; r < 4; r++) {
                float4 p = *(const float4*)(Ps + (r0 + r) * 64 + c4 * 4);
                o[r].x += p.x * v0.x + p.y * v1.x + p.z * v2.x + p.w * v3.x;
                o[r].y += p.x * v0.y + p.y * v1.y + p.z * v2.y + p.w * v3.y;
            }
        }
        __syncthreads();
    }

    // epilogue
#pragma unroll
    for (int r = 0; r < 4; r++) {
        float inv = 1.0f / l[r];
        int q_idx = q0 + r0 + r;
        float2* dst = (float2*)(g_ho + ((size_t)b * Tt + q_idx) * HD) + lane;
        *dst = make_float2(o[r].x * inv, o[r].y * inv);
    }
}

// ---------------------------------------------------------------------------
// Kernel 4: out[m][o] = sum_d g_ho[m][d] * Wred[o][d]
// M=8192, N=1024, K=64. grid (128,16), block 256.
// ---------------------------------------------------------------------------
__global__ void outproj_kernel(float* __restrict__ out) {
    __shared__ float As[64][33];
    __shared__ float Bs[64][33];
    int m0 = blockIdx.x * 64, n0 = blockIdx.y * 64;
    int tid = threadIdx.x;
    int tx = tid & 15, ty = tid >> 4;

    float acc[4][4];
#pragma unroll
    for (int i = 0; i < 4; i++)
#pragma unroll
        for (int j = 0; j < 4; j++) acc[i][j] = 0.f;

    for (int k0 = 0; k0 < 64; k0 += 32) {
#pragma unroll
        for (int i = 0; i < 8; i++) {
            int e = tid + i * 256;
            int mm = e >> 5, kk = e & 31;
            As[mm][kk] = g_ho[(size_t)(m0 + mm) * HD + k0 + kk];
            Bs[mm][kk] = g_wred[(size_t)(n0 + mm) * HD + k0 + kk];
        }
        __syncthreads();
#pragma unroll
        for (int kk = 0; kk < 32; kk++) {
            float a[4], b[4];
#pragma unroll
            for (int i = 0; i < 4; i++) a[i] = As[ty * 4 + i][kk];
#pragma unroll
            for (int j = 0; j < 4; j++) b[j] = Bs[tx * 4 + j][kk];
#pragma unroll
            for (int i = 0; i < 4; i++)
#pragma unroll
                for (int j = 0; j < 4; j++) acc[i][j] += a[i] * b[j];
        }
        __syncthreads();
    }
#pragma unroll
    for (int i = 0; i < 4; i++)
#pragma unroll
        for (int j = 0; j < 4; j++)
            out[(size_t)(m0 + ty * 4 + i) * 1024 + n0 + tx * 4 + j] = acc[i][j];
}

// ---------------------------------------------------------------------------
extern "C" void kernel_launch(void* const* d_in, const int* in_sizes, int n_in,
                              void* d_out, int out_size) {
    (void)in_sizes; (void)n_in; (void)out_size;
    const float* emb  = (const float*)d_in[0];
    const float* Wq   = (const float*)d_in[1];
    const float* Wk   = (const float*)d_in[2];
    const float* Wv   = (const float*)d_in[3];
    const float* Wout = (const float*)d_in[4];
    float* out = (float*)d_out;

    qkv_kernel<<<dim3(128, 1, 3), 256>>>(emb, Wq, Wk, Wv);
    wred_kernel<<<256, 256>>>(Wout);

    size_t smem = (size_t)(2048 + 64 * KSTRIDE + 4096 + 2048) * sizeof(float); // 50176B
    cudaFuncSetAttribute(flash_kernel, cudaFuncAttributeMaxDynamicSharedMemorySize, (int)smem);
    flash_kernel<<<dim3(Tt / BQ, Bb), 256, smem>>>();

    outproj_kernel<<<dim3(128, 16), 256>>>(out);
}

// round 3
// speedup vs baseline: 1.0916x; 1.0916x over previous
#include <cuda_runtime.h>
#include <cstdint>

#define Bb 4
#define Tt 2048
#define Ee 1024
#define HD 64
#define Mrows (Bb*Tt)

#define BQ 32
#define BKV 64
#define KSTRIDE 68

// scratch (no cudaMalloc allowed)
__device__ float g_q[Mrows*HD];
__device__ float g_k[Mrows*HD];
__device__ float g_v[Mrows*HD];
__device__ float g_ho[Mrows*HD];
__device__ float g_wred[Ee*HD];   // [1024][64]

// ---------------------------------------------------------------------------
// mma.sync helpers (portable PTX, runs on tensor pipe at plain sm_103 target)
// ---------------------------------------------------------------------------
__device__ __forceinline__ void mma_tf32(float4& c,
                                         uint32_t a0, uint32_t a1, uint32_t a2, uint32_t a3,
                                         uint32_t b0, uint32_t b1) {
    asm volatile(
        "mma.sync.aligned.m16n8k8.row.col.f32.tf32.tf32.f32 "
        "{%0,%1,%2,%3}, {%4,%5,%6,%7}, {%8,%9}, {%0,%1,%2,%3};"
        : "+f"(c.x), "+f"(c.y), "+f"(c.z), "+f"(c.w)
        : "r"(a0), "r"(a1), "r"(a2), "r"(a3), "r"(b0), "r"(b1));
}

// hi = top-10-mantissa part (exact as tf32); lo = residual (truncated by HW, fine)
__device__ __forceinline__ void split1(float a, uint32_t& h, uint32_t& l) {
    uint32_t ab = __float_as_uint(a);
    uint32_t hb = ab & 0xffffe000u;
    h = hb;
    l = __float_as_uint(a - __uint_as_float(hb));
}

// ---------------------------------------------------------------------------
// Kernel 1: QKV via mma.sync tf32 (3xTF32). C[m][n] = sum_k A[m][k]*W[n][k].
// M=8192, N=64, K=1024. grid (64,3), block 256 (8 warps, warp = 16 rows).
// ---------------------------------------------------------------------------
__global__ void __launch_bounds__(256) qkv_mma(const float* __restrict__ emb,
                                               const float* __restrict__ Wq,
                                               const float* __restrict__ Wk,
                                               const float* __restrict__ Wv) {
    __shared__ float As[128][36];   // (4g+q)%32 distinct -> conflict-free frags
    __shared__ float Bst[32][72];   // k-transposed: (8q+g)%32 distinct

    const float* W = (blockIdx.y == 0) ? Wq : ((blockIdx.y == 1) ? Wk : Wv);
    float* outp = (blockIdx.y == 0) ? g_q : ((blockIdx.y == 1) ? g_k : g_v);
    const int m0 = blockIdx.x * 128;
    const int tid = threadIdx.x;
    const int lane = tid & 31;
    const int wm = (tid >> 5) * 16;          // warp row base
    const int g = lane >> 2, q = lane & 3;

    float4 acc[8];
#pragma unroll
    for (int nb = 0; nb < 8; nb++) acc[nb] = make_float4(0.f, 0.f, 0.f, 0.f);

    const int bn = tid & 63, bkc = tid >> 6;  // B-load mapping

    for (int t = 0; t < 32; t++) {
        const int k0 = t * 32;
        // A tile: 128x32 floats (1024 float4, 4 per thread)
#pragma unroll
        for (int i = 0; i < 4; i++) {
            int idx = tid + i * 256;
            int row = idx >> 3, c4 = idx & 7;
            *(float4*)&As[row][c4 * 4] =
                *(const float4*)(emb + (size_t)(m0 + row) * Ee + k0 + c4 * 4);
        }
        // B tile transposed: W[n][k] -> Bst[k][n]; thread: n=bn, k in [bkc*8, bkc*8+8)
        {
            const float* src = W + (size_t)bn * Ee + k0 + bkc * 8;
            float4 v0 = *(const float4*)(src);
            float4 v1 = *(const float4*)(src + 4);
            int kb = bkc * 8;
            Bst[kb + 0][bn] = v0.x; Bst[kb + 1][bn] = v0.y;
            Bst[kb + 2][bn] = v0.z; Bst[kb + 3][bn] = v0.w;
            Bst[kb + 4][bn] = v1.x; Bst[kb + 5][bn] = v1.y;
            Bst[kb + 6][bn] = v1.z; Bst[kb + 7][bn] = v1.w;
        }
        __syncthreads();

#pragma unroll
        for (int ks = 0; ks < 4; ks++) {
            const int kk = ks * 8;
            uint32_t ah0, al0, ah1, al1, ah2, al2, ah3, al3;
            split1(As[wm + g][kk + q],         ah0, al0);
            split1(As[wm + g + 8][kk + q],     ah1, al1);
            split1(As[wm + g][kk + q + 4],     ah2, al2);
            split1(As[wm + g + 8][kk + q + 4], ah3, al3);
#pragma unroll
            for (int nb = 0; nb < 8; nb++) {
                uint32_t bh0, bl0, bh1, bl1;
                split1(Bst[kk + q][nb * 8 + g],     bh0, bl0);
                split1(Bst[kk + q + 4][nb * 8 + g], bh1, bl1);
                mma_tf32(acc[nb], ah0, ah1, ah2, ah3, bh0, bh1);
                mma_tf32(acc[nb], ah0, ah1, ah2, ah3, bl0, bl1);
                mma_tf32(acc[nb], al0, al1, al2, al3, bh0, bh1);
            }
        }
        __syncthreads();
    }

    // epilogue: c0,c1 -> (row, 2q),(row, 2q+1); c2,c3 -> row+8
    const int row0 = m0 + wm + g;
#pragma unroll
    for (int nb = 0; nb < 8; nb++) {
        int col = nb * 8 + 2 * q;
        *(float2*)(outp + (size_t)row0 * HD + col)       = make_float2(acc[nb].x, acc[nb].y);
        *(float2*)(outp + (size_t)(row0 + 8) * HD + col) = make_float2(acc[nb].z, acc[nb].w);
    }
}

// ---------------------------------------------------------------------------
// Kernel 2: Wred[o][d] = sum_h W_out[o][h*64+d]
// ---------------------------------------------------------------------------
__global__ void wred_kernel(const float* __restrict__ Wout) {
    int idx = blockIdx.x * 256 + threadIdx.x;
    int o = idx >> 6, d = idx & 63;
    float s = 0.f;
#pragma unroll
    for (int h = 0; h < 16; h++) s += Wout[(size_t)o * 1024 + h * 64 + d];
    g_wred[idx] = s;
}

// ---------------------------------------------------------------------------
// Kernel 3: causal flash attention, fp32 (unchanged)
// ---------------------------------------------------------------------------
__global__ void flash_kernel() {
    extern __shared__ float sm[];
    float* Qs = sm;
    float* Ks = sm + 2048;
    float* Vs = sm + 2048 + 64 * KSTRIDE;
    float* Ps = Vs + 4096;

    int b = blockIdx.y;
    int qt = (gridDim.x - 1) - blockIdx.x;
    int q0 = qt * BQ;
    int tid = threadIdx.x;
    int wid = tid >> 5, lane = tid & 31;
    int r0 = wid * 4;

    const float* qbase = g_q + ((size_t)b * Tt + q0) * HD;
#pragma unroll
    for (int i = 0; i < 8; i++) {
        int e = tid + i * 256;
        Qs[e] = qbase[e];
    }

    float m[4], l[4];
    float2 o[4];
#pragma unroll
    for (int r = 0; r < 4; r++) {
        m[r] = -1e30f; l[r] = 0.f; o[r] = make_float2(0.f, 0.f);
    }

    int kmax = q0 + BQ - 1;
    int n_tiles = kmax / BKV + 1;
    __syncthreads();

    for (int t = 0; t < n_tiles; t++) {
        int k0 = t * BKV;
        const float* kb = g_k + ((size_t)b * Tt + k0) * HD;
        const float* vb = g_v + ((size_t)b * Tt + k0) * HD;
#pragma unroll
        for (int i = 0; i < 16; i++) {
            int e = tid + i * 256;
            int c = e >> 6, d = e & 63;
            Ks[c * KSTRIDE + d] = kb[e];
            Vs[e] = vb[e];
        }
        __syncthreads();

        float s[4][2];
#pragma unroll
        for (int r = 0; r < 4; r++) { s[r][0] = 0.f; s[r][1] = 0.f; }
#pragma unroll
        for (int d4 = 0; d4 < 16; d4++) {
            float4 k0v = *(const float4*)(Ks + lane * KSTRIDE + d4 * 4);
            float4 k1v = *(const float4*)(Ks + (lane + 32) * KSTRIDE + d4 * 4);
#pragma unroll
            for (int r = 0; r < 4; r++) {
                float4 qv = *(const float4*)(Qs + (r0 + r) * 64 + d4 * 4);
                s[r][0] += qv.x * k0v.x + qv.y * k0v.y + qv.z * k0v.z + qv.w * k0v.w;
                s[r][1] += qv.x * k1v.x + qv.y * k1v.y + qv.z * k1v.z + qv.w * k1v.w;
            }
        }

        const float scale = 0.125f;
#pragma unroll
        for (int r = 0; r < 4; r++) {
            int q_idx = q0 + r0 + r;
            float s0 = s[r][0] * scale;
            float s1 = s[r][1] * scale;
            if (k0 + lane > q_idx) s0 = -1e30f;
            if (k0 + lane + 32 > q_idx) s1 = -1e30f;
            float mx = fmaxf(s0, s1);
#pragma unroll
            for (int off = 16; off; off >>= 1)
                mx = fmaxf(mx, __shfl_xor_sync(0xffffffffu, mx, off));
            float mn = fmaxf(m[r], mx);
            float p0 = __expf(s0 - mn);
            float p1 = __expf(s1 - mn);
            float rs = p0 + p1;
#pragma unroll
            for (int off = 16; off; off >>= 1)
                rs += __shfl_xor_sync(0xffffffffu, rs, off);
            float alpha = __expf(m[r] - mn);
            m[r] = mn;
            l[r] = l[r] * alpha + rs;
            o[r].x *= alpha;
            o[r].y *= alpha;
            Ps[(r0 + r) * 64 + lane] = p0;
            Ps[(r0 + r) * 64 + lane + 32] = p1;
        }
        __syncwarp();

        const float2* Vs2 = (const float2*)Vs;
#pragma unroll
        for (int c4 = 0; c4 < 16; c4++) {
            float2 v0 = Vs2[(c4 * 4 + 0) * 32 + lane];
            float2 v1 = Vs2[(c4 * 4 + 1) * 32 + lane];
            float2 v2 = Vs2[(c4 * 4 + 2) * 32 + lane];
            float2 v3 = Vs2[(c4 * 4 + 3) * 32 + lane];
#pragma unroll
            for (int r = 0; r < 4; r++) {
                float4 p = *(const float4*)(Ps + (r0 + r) * 64 + c4 * 4);
                o[r].x += p.x * v0.x + p.y * v1.x + p.z * v2.x + p.w * v3.x;
                o[r].y += p.x * v0.y + p.y * v1.y + p.z * v2.y + p.w * v3.y;
            }
        }
        __syncthreads();
    }

#pragma unroll
    for (int r = 0; r < 4; r++) {
        float inv = 1.0f / l[r];
        int q_idx = q0 + r0 + r;
        float2* dst = (float2*)(g_ho + ((size_t)b * Tt + q_idx) * HD) + lane;
        *dst = make_float2(o[r].x * inv, o[r].y * inv);
    }
}

// ---------------------------------------------------------------------------
// Kernel 4: out-proj via mma.sync tf32 (3xTF32).
// C[8192,1024] = HO[8192,64] @ Wred[1024,64]^T. CTA: M=128, N=128, K=64.
// grid (64, 8), block 256 (8 warps, warp = 16 rows x 128 cols).
// Dynamic smem: As[128][68] + Bst[64][136]  (both conflict-free frag patterns)
// ---------------------------------------------------------------------------
#define OP_AS_ELEMS (128*68)
#define OP_BS_ELEMS (64*136)
#define OUTP_SMEM ((OP_AS_ELEMS + OP_BS_ELEMS) * 4)

__global__ void __launch_bounds__(256) outproj_mma(float* __restrict__ out) {
    extern __shared__ float smf[];
    float (*As)[68]  = (float (*)[68])smf;
    float (*Bst)[136] = (float (*)[136])(smf + OP_AS_ELEMS);

    const int m0 = blockIdx.x * 128, n0 = blockIdx.y * 128;
    const int tid = threadIdx.x;
    const int lane = tid & 31;
    const int wm = (tid >> 5) * 16;
    const int g = lane >> 2, q = lane & 3;

    // load A: 128 rows x 64 k = 2048 float4, 8 per thread
#pragma unroll
    for (int i = 0; i < 8; i++) {
        int idx = tid + i * 256;
        int row = idx >> 4, c4 = idx & 15;
        *(float4*)&As[row][c4 * 4] =
            *(const float4*)(g_ho + (size_t)(m0 + row) * HD + c4 * 4);
    }
    // load B transposed: Wred[n][k] -> Bst[k][n]; thread: n = tid&127, half = tid>>7
    {
        const int n = tid & 127, half = tid >> 7;
        const float* src = g_wred + (size_t)(n0 + n) * HD + half * 32;
#pragma unroll
        for (int j4 = 0; j4 < 8; j4++) {
            float4 v = *(const float4*)(src + j4 * 4);
            int kb = half * 32 + j4 * 4;
            Bst[kb + 0][n] = v.x; Bst[kb + 1][n] = v.y;
            Bst[kb + 2][n] = v.z; Bst[kb + 3][n] = v.w;
        }
    }
    __syncthreads();

    float4 acc[16];
#pragma unroll
    for (int nb = 0; nb < 16; nb++) acc[nb] = make_float4(0.f, 0.f, 0.f, 0.f);

#pragma unroll
    for (int ks = 0; ks < 8; ks++) {
        const int kk = ks * 8;
        uint32_t ah0, al0, ah1, al1, ah2, al2, ah3, al3;
        split1(As[wm + g][kk + q],         ah0, al0);
        split1(As[wm + g + 8][kk + q],     ah1, al1);
        split1(As[wm + g][kk + q + 4],     ah2, al2);
        split1(As[wm + g + 8][kk + q + 4], ah3, al3);
#pragma unroll
        for (int nb = 0; nb < 16; nb++) {
            uint32_t bh0, bl0, bh1, bl1;
            split1(Bst[kk + q][nb * 8 + g],     bh0, bl0);
            split1(Bst[kk + q + 4][nb * 8 + g], bh1, bl1);
            mma_tf32(acc[nb], ah0, ah1, ah2, ah3, bh0, bh1);
            mma_tf32(acc[nb], ah0, ah1, ah2, ah3, bl0, bl1);
            mma_tf32(acc[nb], al0, al1, al2, al3, bh0, bh1);
        }
    }

    const int row0 = m0 + wm + g;
#pragma unroll
    for (int nb = 0; nb < 16; nb++) {
        int col = n0 + nb * 8 + 2 * q;
        *(float2*)(out + (size_t)row0 * 1024 + col)       = make_float2(acc[nb].x, acc[nb].y);
        *(float2*)(out + (size_t)(row0 + 8) * 1024 + col) = make_float2(acc[nb].z, acc[nb].w);
    }
}

// ---------------------------------------------------------------------------
extern "C" void kernel_launch(void* const* d_in, const int* in_sizes, int n_in,
                              void* d_out, int out_size) {
    (void)in_sizes; (void)n_in; (void)out_size;
    const float* emb  = (const float*)d_in[0];
    const float* Wq   = (const float*)d_in[1];
    const float* Wk   = (const float*)d_in[2];
    const float* Wv   = (const float*)d_in[3];
    const float* Wout = (const float*)d_in[4];
    float* out = (float*)d_out;

    qkv_mma<<<dim3(64, 3), 256>>>(emb, Wq, Wk, Wv);
    wred_kernel<<<256, 256>>>(Wout);

    size_t smem = (size_t)(2048 + 64 * KSTRIDE + 4096 + 2048) * sizeof(float);
    cudaFuncSetAttribute(flash_kernel, cudaFuncAttributeMaxDynamicSharedMemorySize, (int)smem);
    flash_kernel<<<dim3(Tt / BQ, Bb), 256, smem>>>();

    cudaFuncSetAttribute(outproj_mma, cudaFuncAttributeMaxDynamicSharedMemorySize, OUTP_SMEM);
    outproj_mma<<<dim3(64, 8), 256, OUTP_SMEM>>>(out);
}

// round 4
// speedup vs baseline: 1.4937x; 1.3684x over previous
#include <cuda_runtime.h>
#include <cstdint>

#define Bb 4
#define Tt 2048
#define Ee 1024
#define HD 64
#define Mrows (Bb*Tt)

// scratch (no cudaMalloc allowed)
__device__ float g_q[Mrows*HD];
__device__ float g_k[Mrows*HD];
__device__ float g_v[Mrows*HD];
__device__ float g_ho[Mrows*HD];
__device__ float g_wred[Ee*HD];
__device__ float g_po[2][Mrows*HD];   // split-KV partial O (unnormalized)
__device__ float g_pm[2][Mrows];      // partial row max
__device__ float g_pl[2][Mrows];      // partial row sum

// ---------------------------------------------------------------------------
// mma.sync helpers
// ---------------------------------------------------------------------------
__device__ __forceinline__ void mma_tf32(float4& c,
                                         uint32_t a0, uint32_t a1, uint32_t a2, uint32_t a3,
                                         uint32_t b0, uint32_t b1) {
    asm volatile(
        "mma.sync.aligned.m16n8k8.row.col.f32.tf32.tf32.f32 "
        "{%0,%1,%2,%3}, {%4,%5,%6,%7}, {%8,%9}, {%0,%1,%2,%3};"
        : "+f"(c.x), "+f"(c.y), "+f"(c.z), "+f"(c.w)
        : "r"(a0), "r"(a1), "r"(a2), "r"(a3), "r"(b0), "r"(b1));
}

__device__ __forceinline__ void split1(float a, uint32_t& h, uint32_t& l) {
    uint32_t ab = __float_as_uint(a);
    uint32_t hb = ab & 0xffffe000u;
    h = hb;
    l = __float_as_uint(a - __uint_as_float(hb));
}

// ---------------------------------------------------------------------------
// Kernel 1: QKV via mma.sync tf32 (3xTF32)  [unchanged from R3]
// ---------------------------------------------------------------------------
__global__ void __launch_bounds__(256) qkv_mma(const float* __restrict__ emb,
                                               const float* __restrict__ Wq,
                                               const float* __restrict__ Wk,
                                               const float* __restrict__ Wv) {
    __shared__ float As[128][36];
    __shared__ float Bst[32][72];

    const float* W = (blockIdx.y == 0) ? Wq : ((blockIdx.y == 1) ? Wk : Wv);
    float* outp = (blockIdx.y == 0) ? g_q : ((blockIdx.y == 1) ? g_k : g_v);
    const int m0 = blockIdx.x * 128;
    const int tid = threadIdx.x;
    const int lane = tid & 31;
    const int wm = (tid >> 5) * 16;
    const int g = lane >> 2, q = lane & 3;

    float4 acc[8];
#pragma unroll
    for (int nb = 0; nb < 8; nb++) acc[nb] = make_float4(0.f, 0.f, 0.f, 0.f);

    const int bn = tid & 63, bkc = tid >> 6;

    for (int t = 0; t < 32; t++) {
        const int k0 = t * 32;
#pragma unroll
        for (int i = 0; i < 4; i++) {
            int idx = tid + i * 256;
            int row = idx >> 3, c4 = idx & 7;
            *(float4*)&As[row][c4 * 4] =
                *(const float4*)(emb + (size_t)(m0 + row) * Ee + k0 + c4 * 4);
        }
        {
            const float* src = W + (size_t)bn * Ee + k0 + bkc * 8;
            float4 v0 = *(const float4*)(src);
            float4 v1 = *(const float4*)(src + 4);
            int kb = bkc * 8;
            Bst[kb + 0][bn] = v0.x; Bst[kb + 1][bn] = v0.y;
            Bst[kb + 2][bn] = v0.z; Bst[kb + 3][bn] = v0.w;
            Bst[kb + 4][bn] = v1.x; Bst[kb + 5][bn] = v1.y;
            Bst[kb + 6][bn] = v1.z; Bst[kb + 7][bn] = v1.w;
        }
        __syncthreads();

#pragma unroll
        for (int ks = 0; ks < 4; ks++) {
            const int kk = ks * 8;
            uint32_t ah0, al0, ah1, al1, ah2, al2, ah3, al3;
            split1(As[wm + g][kk + q],         ah0, al0);
            split1(As[wm + g + 8][kk + q],     ah1, al1);
            split1(As[wm + g][kk + q + 4],     ah2, al2);
            split1(As[wm + g + 8][kk + q + 4], ah3, al3);
#pragma unroll
            for (int nb = 0; nb < 8; nb++) {
                uint32_t bh0, bl0, bh1, bl1;
                split1(Bst[kk + q][nb * 8 + g],     bh0, bl0);
                split1(Bst[kk + q + 4][nb * 8 + g], bh1, bl1);
                mma_tf32(acc[nb], ah0, ah1, ah2, ah3, bh0, bh1);
                mma_tf32(acc[nb], ah0, ah1, ah2, ah3, bl0, bl1);
                mma_tf32(acc[nb], al0, al1, al2, al3, bh0, bh1);
            }
        }
        __syncthreads();
    }

    const int row0 = m0 + wm + g;
#pragma unroll
    for (int nb = 0; nb < 8; nb++) {
        int col = nb * 8 + 2 * q;
        *(float2*)(outp + (size_t)row0 * HD + col)       = make_float2(acc[nb].x, acc[nb].y);
        *(float2*)(outp + (size_t)(row0 + 8) * HD + col) = make_float2(acc[nb].z, acc[nb].w);
    }
}

// ---------------------------------------------------------------------------
// Kernel 2: Wred[o][d] = sum_h W_out[o][h*64+d]
// ---------------------------------------------------------------------------
__global__ void wred_kernel(const float* __restrict__ Wout) {
    int idx = blockIdx.x * 256 + threadIdx.x;
    int o = idx >> 6, d = idx & 63;
    float s = 0.f;
#pragma unroll
    for (int h = 0; h < 16; h++) s += Wout[(size_t)o * 1024 + h * 64 + d];
    g_wred[idx] = s;
}

// ---------------------------------------------------------------------------
// Kernel 3: causal flash attention on tensor cores (3xTF32), split-KV 2-way.
// grid (64, 4): blockIdx.x encodes (q-tile, kv-half), heavy q-tiles first.
// block 128 (4 warps x 16 query rows). BQ=64, BKV=64.
// smem: QP[64][72] (Q tile, then reused for P) | Ks[64][68] | Vs[64][72]
// ---------------------------------------------------------------------------
#define PADQ 72
#define PADK 68
#define FL_SMEM ((64*PADQ + 64*PADK + 64*PADQ) * 4)

__global__ void __launch_bounds__(128) flash_mma() {
    extern __shared__ float sm[];
    float* QP = sm;
    float* Ks = sm + 64 * PADQ;
    float* Vs = Ks + 64 * PADK;

    const int b = blockIdx.y;
    const int qt = 31 - (blockIdx.x >> 1);
    const int half = blockIdx.x & 1;
    const int q0 = qt * 64;
    const int tid = threadIdx.x;
    const int lane = tid & 31;
    const int wm = (tid >> 5) * 16;
    const int g = lane >> 2, q = lane & 3;

    const int nt = qt + 1;
    const int n0c = (nt + 1) >> 1;
    const int t_begin = half ? n0c : 0;
    const int t_end = half ? nt : n0c;

    // stage Q tile (pre-scaled by 1/sqrt(64))
    const float* qb = g_q + ((size_t)b * Tt + q0) * HD;
#pragma unroll
    for (int i = 0; i < 8; i++) {
        int idx = tid + i * 128;
        int row = idx >> 4, c4 = (idx & 15) * 4;
        float4 v = *(const float4*)(qb + row * 64 + c4);
        v.x *= 0.125f; v.y *= 0.125f; v.z *= 0.125f; v.w *= 0.125f;
        *(float4*)(QP + row * PADQ + c4) = v;
    }
    __syncthreads();

    // Q fragments -> registers (split hi/lo once)
    uint32_t qh[8][4], ql[8][4];
#pragma unroll
    for (int ks = 0; ks < 8; ks++) {
        split1(QP[(wm + g) * PADQ + ks * 8 + q],         qh[ks][0], ql[ks][0]);
        split1(QP[(wm + g + 8) * PADQ + ks * 8 + q],     qh[ks][1], ql[ks][1]);
        split1(QP[(wm + g) * PADQ + ks * 8 + q + 4],     qh[ks][2], ql[ks][2]);
        split1(QP[(wm + g + 8) * PADQ + ks * 8 + q + 4], qh[ks][3], ql[ks][3]);
    }

    float m0r = -1e30f, m1r = -1e30f, l0r = 0.f, l1r = 0.f;
    float4 o[8];
#pragma unroll
    for (int nb = 0; nb < 8; nb++) o[nb] = make_float4(0.f, 0.f, 0.f, 0.f);

    for (int t = t_begin; t < t_end; t++) {
        const int k0 = t * 64;
        __syncthreads();   // K/V/QP(P region reads done, Q frag reads done on iter 0)
        const float* kb = g_k + ((size_t)b * Tt + k0) * HD;
        const float* vb = g_v + ((size_t)b * Tt + k0) * HD;
#pragma unroll
        for (int i = 0; i < 8; i++) {
            int idx = tid + i * 128;
            int row = idx >> 4, c4 = (idx & 15) * 4;
            *(float4*)(Ks + row * PADK + c4) = *(const float4*)(kb + row * 64 + c4);
            *(float4*)(Vs + row * PADQ + c4) = *(const float4*)(vb + row * 64 + c4);
        }
        __syncthreads();

        // S = Q K^T  (16x64 per warp)
        float4 s[8];
#pragma unroll
        for (int nb = 0; nb < 8; nb++) s[nb] = make_float4(0.f, 0.f, 0.f, 0.f);
#pragma unroll
        for (int ks = 0; ks < 8; ks++) {
#pragma unroll
            for (int nb = 0; nb < 8; nb++) {
                float kv0 = Ks[(nb * 8 + g) * PADK + ks * 8 + q];
                float kv1 = Ks[(nb * 8 + g) * PADK + ks * 8 + q + 4];
                uint32_t bh0, bl0, bh1, bl1;
                split1(kv0, bh0, bl0);
                split1(kv1, bh1, bl1);
                mma_tf32(s[nb], qh[ks][0], qh[ks][1], qh[ks][2], qh[ks][3], bh0, bh1);
                mma_tf32(s[nb], qh[ks][0], qh[ks][1], qh[ks][2], qh[ks][3], bl0, bl1);
                mma_tf32(s[nb], ql[ks][0], ql[ks][1], ql[ks][2], ql[ks][3], bh0, bh1);
            }
        }

        // causal mask (diagonal tile only)
        if (k0 == q0) {
            const int r0g = q0 + wm + g;
#pragma unroll
            for (int nb = 0; nb < 8; nb++) {
                int c = k0 + nb * 8 + 2 * q;
                if (c > r0g)         s[nb].x = -1e30f;
                if (c + 1 > r0g)     s[nb].y = -1e30f;
                if (c > r0g + 8)     s[nb].z = -1e30f;
                if (c + 1 > r0g + 8) s[nb].w = -1e30f;
            }
        }

        // online softmax
        float mx0 = -1e30f, mx1 = -1e30f;
#pragma unroll
        for (int nb = 0; nb < 8; nb++) {
            mx0 = fmaxf(mx0, fmaxf(s[nb].x, s[nb].y));
            mx1 = fmaxf(mx1, fmaxf(s[nb].z, s[nb].w));
        }
        mx0 = fmaxf(mx0, __shfl_xor_sync(0xffffffffu, mx0, 1));
        mx0 = fmaxf(mx0, __shfl_xor_sync(0xffffffffu, mx0, 2));
        mx1 = fmaxf(mx1, __shfl_xor_sync(0xffffffffu, mx1, 1));
        mx1 = fmaxf(mx1, __shfl_xor_sync(0xffffffffu, mx1, 2));
        float mn0 = fmaxf(m0r, mx0), mn1 = fmaxf(m1r, mx1);
        float a0 = __expf(m0r - mn0), a1 = __expf(m1r - mn1);
        m0r = mn0; m1r = mn1;

        float rs0 = 0.f, rs1 = 0.f;
#pragma unroll
        for (int nb = 0; nb < 8; nb++) {
            float p0 = __expf(s[nb].x - mn0);
            float p1 = __expf(s[nb].y - mn0);
            float p2 = __expf(s[nb].z - mn1);
            float p3 = __expf(s[nb].w - mn1);
            rs0 += p0 + p1;
            rs1 += p2 + p3;
            *(float2*)(QP + (wm + g) * PADQ + nb * 8 + 2 * q)     = make_float2(p0, p1);
            *(float2*)(QP + (wm + g + 8) * PADQ + nb * 8 + 2 * q) = make_float2(p2, p3);
        }
        rs0 += __shfl_xor_sync(0xffffffffu, rs0, 1);
        rs0 += __shfl_xor_sync(0xffffffffu, rs0, 2);
        rs1 += __shfl_xor_sync(0xffffffffu, rs1, 1);
        rs1 += __shfl_xor_sync(0xffffffffu, rs1, 2);
        l0r = l0r * a0 + rs0;
        l1r = l1r * a1 + rs1;
#pragma unroll
        for (int nb = 0; nb < 8; nb++) {
            o[nb].x *= a0; o[nb].y *= a0;
            o[nb].z *= a1; o[nb].w *= a1;
        }
        __syncwarp();

        // O += P V
#pragma unroll
        for (int ks = 0; ks < 8; ks++) {
            uint32_t ph0, pl0, ph1, pl1, ph2, pl2, ph3, pl3;
            split1(QP[(wm + g) * PADQ + ks * 8 + q],         ph0, pl0);
            split1(QP[(wm + g + 8) * PADQ + ks * 8 + q],     ph1, pl1);
            split1(QP[(wm + g) * PADQ + ks * 8 + q + 4],     ph2, pl2);
            split1(QP[(wm + g + 8) * PADQ + ks * 8 + q + 4], ph3, pl3);
#pragma unroll
            for (int nb = 0; nb < 8; nb++) {
                float v0 = Vs[(ks * 8 + q) * PADQ + nb * 8 + g];
                float v1 = Vs[(ks * 8 + q + 4) * PADQ + nb * 8 + g];
                uint32_t vh0, vl0, vh1, vl1;
                split1(v0, vh0, vl0);
                split1(v1, vh1, vl1);
                mma_tf32(o[nb], ph0, ph1, ph2, ph3, vh0, vh1);
                mma_tf32(o[nb], ph0, ph1, ph2, ph3, vl0, vl1);
                mma_tf32(o[nb], pl0, pl1, pl2, pl3, vh0, vh1);
            }
        }
    }

    // epilogue: unnormalized partials
    const size_t row0 = (size_t)b * Tt + q0 + wm + g;
    float* po = g_po[half];
#pragma unroll
    for (int nb = 0; nb < 8; nb++) {
        int col = nb * 8 + 2 * q;
        *(float2*)(po + row0 * HD + col)       = make_float2(o[nb].x, o[nb].y);
        *(float2*)(po + (row0 + 8) * HD + col) = make_float2(o[nb].z, o[nb].w);
    }
    if (q == 0) {
        g_pm[half][row0] = m0r;     g_pl[half][row0] = l0r;
        g_pm[half][row0 + 8] = m1r; g_pl[half][row0 + 8] = l1r;
    }
}

// ---------------------------------------------------------------------------
// Kernel 3b: combine split-KV partials -> g_ho
// ---------------------------------------------------------------------------
__global__ void combine_kernel() {
    int idx = blockIdx.x * 256 + threadIdx.x;   // Mrows*32 float2 slots
    int row = idx >> 5;
    int col = (idx & 31) * 2;
    float m0 = g_pm[0][row], m1 = g_pm[1][row];
    float mx = fmaxf(m0, m1);
    float w0 = __expf(m0 - mx), w1 = __expf(m1 - mx);
    float l = g_pl[0][row] * w0 + g_pl[1][row] * w1;
    float inv = 1.f / l;
    float2 a = *(const float2*)(g_po[0] + (size_t)row * HD + col);
    float2 c = *(const float2*)(g_po[1] + (size_t)row * HD + col);
    *(float2*)(g_ho + (size_t)row * HD + col) =
        make_float2((a.x * w0 + c.x * w1) * inv, (a.y * w0 + c.y * w1) * inv);
}

// ---------------------------------------------------------------------------
// Kernel 4: out-proj via mma.sync tf32 (3xTF32)  [unchanged from R3]
// ---------------------------------------------------------------------------
#define OP_AS_ELEMS (128*68)
#define OP_BS_ELEMS (64*136)
#define OUTP_SMEM ((OP_AS_ELEMS + OP_BS_ELEMS) * 4)

__global__ void __launch_bounds__(256) outproj_mma(float* __restrict__ out) {
    extern __shared__ float smf[];
    float (*As)[68]  = (float (*)[68])smf;
    float (*Bst)[136] = (float (*)[136])(smf + OP_AS_ELEMS);

    const int m0 = blockIdx.x * 128, n0 = blockIdx.y * 128;
    const int tid = threadIdx.x;
    const int lane = tid & 31;
    const int wm = (tid >> 5) * 16;
    const int g = lane >> 2, q = lane & 3;

#pragma unroll
    for (int i = 0; i < 8; i++) {
        int idx = tid + i * 256;
        int row = idx >> 4, c4 = idx & 15;
        *(float4*)&As[row][c4 * 4] =
            *(const float4*)(g_ho + (size_t)(m0 + row) * HD + c4 * 4);
    }
    {
        const int n = tid & 127, half = tid >> 7;
        const float* src = g_wred + (size_t)(n0 + n) * HD + half * 32;
#pragma unroll
        for (int j4 = 0; j4 < 8; j4++) {
            float4 v = *(const float4*)(src + j4 * 4);
            int kb = half * 32 + j4 * 4;
            Bst[kb + 0][n] = v.x; Bst[kb + 1][n] = v.y;
            Bst[kb + 2][n] = v.z; Bst[kb + 3][n] = v.w;
        }
    }
    __syncthreads();

    float4 acc[16];
#pragma unroll
    for (int nb = 0; nb < 16; nb++) acc[nb] = make_float4(0.f, 0.f, 0.f, 0.f);

#pragma unroll
    for (int ks = 0; ks < 8; ks++) {
        const int kk = ks * 8;
        uint32_t ah0, al0, ah1, al1, ah2, al2, ah3, al3;
        split1(As[wm + g][kk + q],         ah0, al0);
        split1(As[wm + g + 8][kk + q],     ah1, al1);
        split1(As[wm + g][kk + q + 4],     ah2, al2);
        split1(As[wm + g + 8][kk + q + 4], ah3, al3);
#pragma unroll
        for (int nb = 0; nb < 16; nb++) {
            uint32_t bh0, bl0, bh1, bl1;
            split1(Bst[kk + q][nb * 8 + g],     bh0, bl0);
            split1(Bst[kk + q + 4][nb * 8 + g], bh1, bl1);
            mma_tf32(acc[nb], ah0, ah1, ah2, ah3, bh0, bh1);
            mma_tf32(acc[nb], ah0, ah1, ah2, ah3, bl0, bl1);
            mma_tf32(acc[nb], al0, al1, al2, al3, bh0, bh1);
        }
    }

    const int row0 = m0 + wm + g;
#pragma unroll
    for (int nb = 0; nb < 16; nb++) {
        int col = n0 + nb * 8 + 2 * q;
        *(float2*)(out + (size_t)row0 * 1024 + col)       = make_float2(acc[nb].x, acc[nb].y);
        *(float2*)(out + (size_t)(row0 + 8) * 1024 + col) = make_float2(acc[nb].z, acc[nb].w);
    }
}

// ---------------------------------------------------------------------------
extern "C" void kernel_launch(void* const* d_in, const int* in_sizes, int n_in,
                              void* d_out, int out_size) {
    (void)in_sizes; (void)n_in; (void)out_size;
    const float* emb  = (const float*)d_in[0];
    const float* Wq   = (const float*)d_in[1];
    const float* Wk   = (const float*)d_in[2];
    const float* Wv   = (const float*)d_in[3];
    const float* Wout = (const float*)d_in[4];
    float* out = (float*)d_out;

    qkv_mma<<<dim3(64, 3), 256>>>(emb, Wq, Wk, Wv);
    wred_kernel<<<256, 256>>>(Wout);

    cudaFuncSetAttribute(flash_mma, cudaFuncAttributeMaxDynamicSharedMemorySize, FL_SMEM);
    flash_mma<<<dim3(64, 4), 128, FL_SMEM>>>();
    combine_kernel<<<Mrows * 32 / 256, 256>>>();

    cudaFuncSetAttribute(outproj_mma, cudaFuncAttributeMaxDynamicSharedMemorySize, OUTP_SMEM);
    outproj_mma<<<dim3(64, 8), 256, OUTP_SMEM>>>(out);
}

// round 5
// speedup vs baseline: 2.2791x; 1.5258x over previous
#include <cuda_runtime.h>
#include <cuda_bf16.h>
#include <cstdint>

#define Bb 4
#define Tt 2048
#define Ee 1024
#define HD 64
#define Mrows (Bb*Tt)
#define FPAD 36   // u32 row stride: 36 % 32 == 4 -> conflict-free fragment reads

// scratch (no cudaMalloc allowed)
__device__ __align__(16) uint32_t g_qh[Mrows*32];
__device__ __align__(16) uint32_t g_ql[Mrows*32];
__device__ __align__(16) uint32_t g_kh[Mrows*32];
__device__ __align__(16) uint32_t g_kl[Mrows*32];
__device__ __align__(16) float    g_v [Mrows*HD];
__device__ __align__(16) uint32_t g_wbh[192*512];   // [Wq|Wk|Wv] bf16x2 hi
__device__ __align__(16) uint32_t g_wbl[192*512];
__device__ __align__(16) uint32_t g_wrh[1024*32];   // Wred bf16x2 hi
__device__ __align__(16) uint32_t g_wrl[1024*32];
__device__ __align__(16) uint32_t g_hoh[Mrows*32];
__device__ __align__(16) uint32_t g_hol[Mrows*32];
__device__ __align__(16) float g_po[2][Mrows*HD];
__device__ float g_pm[2][Mrows];
__device__ float g_pl[2][Mrows];

// ---------------------------------------------------------------------------
__device__ __forceinline__ void mma_bf16(float4& c,
                                         uint32_t a0, uint32_t a1, uint32_t a2, uint32_t a3,
                                         uint32_t b0, uint32_t b1) {
    asm volatile(
        "mma.sync.aligned.m16n8k16.row.col.f32.bf16.bf16.f32 "
        "{%0,%1,%2,%3}, {%4,%5,%6,%7}, {%8,%9}, {%0,%1,%2,%3};"
        : "+f"(c.x), "+f"(c.y), "+f"(c.z), "+f"(c.w)
        : "r"(a0), "r"(a1), "r"(a2), "r"(a3), "r"(b0), "r"(b1));
}

// split pair of floats into packed bf16x2 hi + bf16x2 lo (residual)
__device__ __forceinline__ void bsplit2(float a0, float a1, uint32_t& h, uint32_t& l) {
    __nv_bfloat162 hh = __floats2bfloat162_rn(a0, a1);
    float r0 = a0 - __bfloat162float(hh.x);
    float r1 = a1 - __bfloat162float(hh.y);
    __nv_bfloat162 ll = __floats2bfloat162_rn(r0, r1);
    h = *reinterpret_cast<uint32_t*>(&hh);
    l = *reinterpret_cast<uint32_t*>(&ll);
}

// ---------------------------------------------------------------------------
// Kernel 0: pre-split weights. idx<98304: W[q|k|v] -> g_wbh/l. Else Wred fold.
// ---------------------------------------------------------------------------
__global__ void prep_kernel(const float* __restrict__ Wq, const float* __restrict__ Wk,
                            const float* __restrict__ Wv, const float* __restrict__ Wout) {
    int idx = blockIdx.x * 256 + threadIdx.x;   // 131072 total
    if (idx < 98304) {
        int n = idx >> 9, k2 = idx & 511;
        const float* w = (n < 64) ? Wq : ((n < 128) ? Wk : Wv);
        int r = n & 63;
        float a0 = w[(size_t)r * 1024 + 2 * k2];
        float a1 = w[(size_t)r * 1024 + 2 * k2 + 1];
        uint32_t h, l; bsplit2(a0, a1, h, l);
        g_wbh[idx] = h; g_wbl[idx] = l;
    } else {
        int j = idx - 98304;                    // 32768
        int o = j >> 5, d2 = j & 31;
        float s0 = 0.f, s1 = 0.f;
#pragma unroll
        for (int h = 0; h < 16; h++) {
            s0 += Wout[(size_t)o * 1024 + h * 64 + 2 * d2];
            s1 += Wout[(size_t)o * 1024 + h * 64 + 2 * d2 + 1];
        }
        uint32_t h, l; bsplit2(s0, s1, h, l);
        g_wrh[j] = h; g_wrl[j] = l;
    }
}

// ---------------------------------------------------------------------------
// Kernel 1: fused QKV. C[8192,192] = emb @ [Wq|Wk|Wv]^T via 3xBF16.
// grid 128 (64 rows each), block 256: warp = 16 rows x 96 cols (12 nb).
// Epilogue: q (x0.125) and k written as bf16 hi/lo pairs; v as f32.
// smem u32: Ah[64*36] Al Bh[192*36] Bl = 73728 B
// ---------------------------------------------------------------------------
#define QKV_SMEM ((64*FPAD*2 + 192*FPAD*2) * 4)

__global__ void __launch_bounds__(256) qkv_fused(const float* __restrict__ emb) {
    extern __shared__ uint32_t smu[];
    uint32_t* Ah = smu;
    uint32_t* Al = Ah + 64 * FPAD;
    uint32_t* Bh = Al + 64 * FPAD;
    uint32_t* Bl = Bh + 192 * FPAD;

    const int m0 = blockIdx.x * 64;
    const int tid = threadIdx.x;
    const int lane = tid & 31;
    const int w = tid >> 5;
    const int wm = (w & 3) * 16;
    const int colbase = (w >> 2) * 96;
    const int g = lane >> 2, q = lane & 3;

    float4 acc[12];
#pragma unroll
    for (int nb = 0; nb < 12; nb++) acc[nb] = make_float4(0.f, 0.f, 0.f, 0.f);

    for (int kt = 0; kt < 16; kt++) {
        __syncthreads();
        // A: 64 rows x 64 floats -> split into bf16x2 pairs
#pragma unroll
        for (int i = 0; i < 4; i++) {
            int idx = tid + i * 256;
            int row = idx >> 4, c4 = idx & 15;
            float4 v = *(const float4*)(emb + (size_t)(m0 + row) * Ee + kt * 64 + c4 * 4);
            uint32_t h0, l0, h1, l1;
            bsplit2(v.x, v.y, h0, l0);
            bsplit2(v.z, v.w, h1, l1);
            Ah[row * FPAD + c4 * 2] = h0; Ah[row * FPAD + c4 * 2 + 1] = h1;
            Al[row * FPAD + c4 * 2] = l0; Al[row * FPAD + c4 * 2 + 1] = l1;
        }
        // B: 192 rows x 32 u32, hi then lo (pre-split gmem)
#pragma unroll
        for (int i = 0; i < 6; i++) {
            int j = tid + i * 256;
            int row = j >> 3, c = j & 7;
            *(uint4*)(Bh + row * FPAD + c * 4) =
                *(const uint4*)(g_wbh + (size_t)row * 512 + kt * 32 + c * 4);
        }
#pragma unroll
        for (int i = 0; i < 6; i++) {
            int j = tid + i * 256;
            int row = j >> 3, c = j & 7;
            *(uint4*)(Bl + row * FPAD + c * 4) =
                *(const uint4*)(g_wbl + (size_t)row * 512 + kt * 32 + c * 4);
        }
        __syncthreads();

#pragma unroll
        for (int ks = 0; ks < 4; ks++) {
            const int kb = ks * 8 + q;
            uint32_t ah0 = Ah[(wm + g) * FPAD + kb];
            uint32_t ah1 = Ah[(wm + g + 8) * FPAD + kb];
            uint32_t ah2 = Ah[(wm + g) * FPAD + kb + 4];
            uint32_t ah3 = Ah[(wm + g + 8) * FPAD + kb + 4];
            uint32_t al0 = Al[(wm + g) * FPAD + kb];
            uint32_t al1 = Al[(wm + g + 8) * FPAD + kb];
            uint32_t al2 = Al[(wm + g) * FPAD + kb + 4];
            uint32_t al3 = Al[(wm + g + 8) * FPAD + kb + 4];
#pragma unroll
            for (int nb = 0; nb < 12; nb++) {
                const int n = colbase + nb * 8 + g;
                uint32_t bh0 = Bh[n * FPAD + kb];
                uint32_t bh1 = Bh[n * FPAD + kb + 4];
                uint32_t bl0 = Bl[n * FPAD + kb];
                uint32_t bl1 = Bl[n * FPAD + kb + 4];
                mma_bf16(acc[nb], ah0, ah1, ah2, ah3, bh0, bh1);
                mma_bf16(acc[nb], ah0, ah1, ah2, ah3, bl0, bl1);
                mma_bf16(acc[nb], al0, al1, al2, al3, bh0, bh1);
            }
        }
    }

    // epilogue
    const size_t r0 = m0 + wm + g;
#pragma unroll
    for (int nb = 0; nb < 12; nb++) {
        int gcol = colbase + nb * 8 + 2 * q;
        int sec = gcol >> 6;
        int lc = gcol & 63;
        float4 c = acc[nb];
        if (sec == 0) {          // Q, pre-scaled
            uint32_t h, l;
            bsplit2(c.x * 0.125f, c.y * 0.125f, h, l);
            g_qh[r0 * 32 + lc / 2] = h; g_ql[r0 * 32 + lc / 2] = l;
            bsplit2(c.z * 0.125f, c.w * 0.125f, h, l);
            g_qh[(r0 + 8) * 32 + lc / 2] = h; g_ql[(r0 + 8) * 32 + lc / 2] = l;
        } else if (sec == 1) {   // K
            uint32_t h, l;
            bsplit2(c.x, c.y, h, l);
            g_kh[r0 * 32 + lc / 2] = h; g_kl[r0 * 32 + lc / 2] = l;
            bsplit2(c.z, c.w, h, l);
            g_kh[(r0 + 8) * 32 + lc / 2] = h; g_kl[(r0 + 8) * 32 + lc / 2] = l;
        } else {                 // V (f32, flash transposes+splits it)
            *(float2*)(g_v + r0 * HD + lc)       = make_float2(c.x, c.y);
            *(float2*)(g_v + (r0 + 8) * HD + lc) = make_float2(c.z, c.w);
        }
    }
}

// ---------------------------------------------------------------------------
// Kernel 2: flash attention, 3xBF16 mma, split-KV 2-way.
// grid (64,4), block 128 (4 warps x 16 rows). BQ=BKV=64.
// smem u32: Kh Kl Vth Vtl Ph Pl each [64*36] = 55296 B
// ---------------------------------------------------------------------------
#define FL_SMEM (6 * 64 * FPAD * 4)

__global__ void __launch_bounds__(128) flash_mma() {
    extern __shared__ uint32_t smu[];
    uint32_t* Kh  = smu;
    uint32_t* Kl  = Kh  + 64 * FPAD;
    uint32_t* Vth = Kl  + 64 * FPAD;
    uint32_t* Vtl = Vth + 64 * FPAD;
    uint32_t* Ph  = Vtl + 64 * FPAD;
    uint32_t* Pl  = Ph  + 64 * FPAD;

    const int b = blockIdx.y;
    const int qt = 31 - (blockIdx.x >> 1);
    const int half = blockIdx.x & 1;
    const int q0 = qt * 64;
    const int tid = threadIdx.x;
    const int lane = tid & 31;
    const int wm = (tid >> 5) * 16;
    const int g = lane >> 2, q = lane & 3;

    const int nt = qt + 1;
    const int n0c = (nt + 1) >> 1;
    const int t_begin = half ? n0c : 0;
    const int t_end = half ? nt : n0c;

    // Q fragments straight from pre-split gmem
    const size_t qrow0 = (size_t)b * Tt + q0;
    uint32_t qh[4][4], ql[4][4];
#pragma unroll
    for (int ks = 0; ks < 4; ks++) {
        const int kb = ks * 8 + q;
        qh[ks][0] = g_qh[(qrow0 + wm + g) * 32 + kb];
        qh[ks][1] = g_qh[(qrow0 + wm + g + 8) * 32 + kb];
        qh[ks][2] = g_qh[(qrow0 + wm + g) * 32 + kb + 4];
        qh[ks][3] = g_qh[(qrow0 + wm + g + 8) * 32 + kb + 4];
        ql[ks][0] = g_ql[(qrow0 + wm + g) * 32 + kb];
        ql[ks][1] = g_ql[(qrow0 + wm + g + 8) * 32 + kb];
        ql[ks][2] = g_ql[(qrow0 + wm + g) * 32 + kb + 4];
        ql[ks][3] = g_ql[(qrow0 + wm + g + 8) * 32 + kb + 4];
    }

    float m0r = -1e30f, m1r = -1e30f, l0r = 0.f, l1r = 0.f;
    float4 o[8];
#pragma unroll
    for (int nb = 0; nb < 8; nb++) o[nb] = make_float4(0.f, 0.f, 0.f, 0.f);

    for (int t = t_begin; t < t_end; t++) {
        const int k0 = t * 64;
        __syncthreads();
        // K tiles: straight u32 copy of pre-split K
        {
            const uint4* sh = (const uint4*)(g_kh + ((size_t)b * Tt + k0) * 32);
            const uint4* sl = (const uint4*)(g_kl + ((size_t)b * Tt + k0) * 32);
#pragma unroll
            for (int i = 0; i < 4; i++) {
                int idx = tid + i * 128;
                int row = idx >> 3, c = idx & 7;
                *(uint4*)(Kh + row * FPAD + c * 4) = sh[row * 8 + c];
                *(uint4*)(Kl + row * FPAD + c * 4) = sl[row * 8 + c];
            }
        }
        // V: transpose + split. Vt[hd][seq2] = bf16x2(V[2s2][hd], V[2s2+1][hd])
        {
            const float* vb = g_v + ((size_t)b * Tt + k0) * HD;
#pragma unroll
            for (int i = 0; i < 16; i++) {
                int idx = tid + i * 128;
                int hd = idx & 63, s2 = idx >> 6;
                float v0 = vb[(2 * s2) * 64 + hd];
                float v1 = vb[(2 * s2 + 1) * 64 + hd];
                uint32_t h, l; bsplit2(v0, v1, h, l);
                Vth[hd * FPAD + s2] = h;
                Vtl[hd * FPAD + s2] = l;
            }
        }
        __syncthreads();

        // S = Q K^T
        float4 s[8];
#pragma unroll
        for (int nb = 0; nb < 8; nb++) s[nb] = make_float4(0.f, 0.f, 0.f, 0.f);
#pragma unroll
        for (int ks = 0; ks < 4; ks++) {
            const int kb = ks * 8 + q;
#pragma unroll
            for (int nb = 0; nb < 8; nb++) {
                const int n = nb * 8 + g;
                uint32_t bh0 = Kh[n * FPAD + kb];
                uint32_t bh1 = Kh[n * FPAD + kb + 4];
                uint32_t bl0 = Kl[n * FPAD + kb];
                uint32_t bl1 = Kl[n * FPAD + kb + 4];
                mma_bf16(s[nb], qh[ks][0], qh[ks][1], qh[ks][2], qh[ks][3], bh0, bh1);
                mma_bf16(s[nb], qh[ks][0], qh[ks][1], qh[ks][2], qh[ks][3], bl0, bl1);
                mma_bf16(s[nb], ql[ks][0], ql[ks][1], ql[ks][2], ql[ks][3], bh0, bh1);
            }
        }

        // causal mask (diagonal tile only)
        if (k0 == q0) {
            const int r0g = q0 + wm + g;
#pragma unroll
            for (int nb = 0; nb < 8; nb++) {
                int c = k0 + nb * 8 + 2 * q;
                if (c > r0g)         s[nb].x = -1e30f;
                if (c + 1 > r0g)     s[nb].y = -1e30f;
                if (c > r0g + 8)     s[nb].z = -1e30f;
                if (c + 1 > r0g + 8) s[nb].w = -1e30f;
            }
        }

        // online softmax
        float mx0 = -1e30f, mx1 = -1e30f;
#pragma unroll
        for (int nb = 0; nb < 8; nb++) {
            mx0 = fmaxf(mx0, fmaxf(s[nb].x, s[nb].y));
            mx1 = fmaxf(mx1, fmaxf(s[nb].z, s[nb].w));
        }
        mx0 = fmaxf(mx0, __shfl_xor_sync(0xffffffffu, mx0, 1));
        mx0 = fmaxf(mx0, __shfl_xor_sync(0xffffffffu, mx0, 2));
        mx1 = fmaxf(mx1, __shfl_xor_sync(0xffffffffu, mx1, 1));
        mx1 = fmaxf(mx1, __shfl_xor_sync(0xffffffffu, mx1, 2));
        float mn0 = fmaxf(m0r, mx0), mn1 = fmaxf(m1r, mx1);
        float a0 = __expf(m0r - mn0), a1 = __expf(m1r - mn1);
        m0r = mn0; m1r = mn1;

        float rs0 = 0.f, rs1 = 0.f;
#pragma unroll
        for (int nb = 0; nb < 8; nb++) {
            float p0 = __expf(s[nb].x - mn0);
            float p1 = __expf(s[nb].y - mn0);
            float p2 = __expf(s[nb].z - mn1);
            float p3 = __expf(s[nb].w - mn1);
            rs0 += p0 + p1;
            rs1 += p2 + p3;
            uint32_t h, l;
            bsplit2(p0, p1, h, l);
            Ph[(wm + g) * FPAD + nb * 4 + q] = h;
            Pl[(wm + g) * FPAD + nb * 4 + q] = l;
            bsplit2(p2, p3, h, l);
            Ph[(wm + g + 8) * FPAD + nb * 4 + q] = h;
            Pl[(wm + g + 8) * FPAD + nb * 4 + q] = l;
        }
        rs0 += __shfl_xor_sync(0xffffffffu, rs0, 1);
        rs0 += __shfl_xor_sync(0xffffffffu, rs0, 2);
        rs1 += __shfl_xor_sync(0xffffffffu, rs1, 1);
        rs1 += __shfl_xor_sync(0xffffffffu, rs1, 2);
        l0r = l0r * a0 + rs0;
        l1r = l1r * a1 + rs1;
#pragma unroll
        for (int nb = 0; nb < 8; nb++) {
            o[nb].x *= a0; o[nb].y *= a0;
            o[nb].z *= a1; o[nb].w *= a1;
        }
        __syncwarp();

        // O += P V
#pragma unroll
        for (int ks = 0; ks < 4; ks++) {
            const int kb = ks * 8 + q;
            uint32_t ph0 = Ph[(wm + g) * FPAD + kb];
            uint32_t ph1 = Ph[(wm + g + 8) * FPAD + kb];
            uint32_t ph2 = Ph[(wm + g) * FPAD + kb + 4];
            uint32_t ph3 = Ph[(wm + g + 8) * FPAD + kb + 4];
            uint32_t pl0 = Pl[(wm + g) * FPAD + kb];
            uint32_t pl1 = Pl[(wm + g + 8) * FPAD + kb];
            uint32_t pl2 = Pl[(wm + g) * FPAD + kb + 4];
            uint32_t pl3 = Pl[(wm + g + 8) * FPAD + kb + 4];
#pragma unroll
            for (int nb = 0; nb < 8; nb++) {
                const int n = nb * 8 + g;
                uint32_t vh0 = Vth[n * FPAD + kb];
                uint32_t vh1 = Vth[n * FPAD + kb + 4];
                uint32_t vl0 = Vtl[n * FPAD + kb];
                uint32_t vl1 = Vtl[n * FPAD + kb + 4];
                mma_bf16(o[nb], ph0, ph1, ph2, ph3, vh0, vh1);
                mma_bf16(o[nb], ph0, ph1, ph2, ph3, vl0, vl1);
                mma_bf16(o[nb], pl0, pl1, pl2, pl3, vh0, vh1);
            }
        }
    }

    // epilogue: unnormalized partials
    const size_t row0 = (size_t)b * Tt + q0 + wm + g;
    float* po = g_po[half];
#pragma unroll
    for (int nb = 0; nb < 8; nb++) {
        int col = nb * 8 + 2 * q;
        *(float2*)(po + row0 * HD + col)       = make_float2(o[nb].x, o[nb].y);
        *(float2*)(po + (row0 + 8) * HD + col) = make_float2(o[nb].z, o[nb].w);
    }
    if (q == 0) {
        g_pm[half][row0] = m0r;     g_pl[half][row0] = l0r;
        g_pm[half][row0 + 8] = m1r; g_pl[half][row0 + 8] = l1r;
    }
}

// ---------------------------------------------------------------------------
// Kernel 3: combine split-KV partials -> pre-split bf16 HO
// ---------------------------------------------------------------------------
__global__ void combine_kernel() {
    int idx = blockIdx.x * 256 + threadIdx.x;   // Mrows*32
    int row = idx >> 5;
    int d2 = idx & 31;
    float m0 = g_pm[0][row], m1 = g_pm[1][row];
    float mx = fmaxf(m0, m1);
    float w0 = __expf(m0 - mx), w1 = __expf(m1 - mx);
    float l = g_pl[0][row] * w0 + g_pl[1][row] * w1;
    float inv = 1.f / l;
    float2 a = *(const float2*)(g_po[0] + (size_t)row * HD + 2 * d2);
    float2 c = *(const float2*)(g_po[1] + (size_t)row * HD + 2 * d2);
    float o0 = (a.x * w0 + c.x * w1) * inv;
    float o1 = (a.y * w0 + c.y * w1) * inv;
    uint32_t h, lo; bsplit2(o0, o1, h, lo);
    g_hoh[idx] = h; g_hol[idx] = lo;
}

// ---------------------------------------------------------------------------
// Kernel 4: out-proj 3xBF16. C[8192,1024] = HO @ Wred^T. CTA 128x128, K=64.
// grid (64,8), block 256. smem: Ah Al Bh Bl each [128*36] u32 = 73728 B
// ---------------------------------------------------------------------------
#define OUTP_SMEM (4 * 128 * FPAD * 4)

__global__ void __launch_bounds__(256) outproj_mma(float* __restrict__ out) {
    extern __shared__ uint32_t smu[];
    uint32_t* Ah = smu;
    uint32_t* Al = Ah + 128 * FPAD;
    uint32_t* Bh = Al + 128 * FPAD;
    uint32_t* Bl = Bh + 128 * FPAD;

    const int m0 = blockIdx.x * 128, n0 = blockIdx.y * 128;
    const int tid = threadIdx.x;
    const int lane = tid & 31;
    const int wm = (tid >> 5) * 16;
    const int g = lane >> 2, q = lane & 3;

    // loads: each tensor 128 rows x 8 uint4
#pragma unroll
    for (int i = 0; i < 4; i++) {
        int j = tid + i * 256;
        int row = j >> 3, c = j & 7;
        *(uint4*)(Ah + row * FPAD + c * 4) = *(const uint4*)(g_hoh + (size_t)(m0 + row) * 32 + c * 4);
        *(uint4*)(Al + row * FPAD + c * 4) = *(const uint4*)(g_hol + (size_t)(m0 + row) * 32 + c * 4);
        *(uint4*)(Bh + row * FPAD + c * 4) = *(const uint4*)(g_wrh + (size_t)(n0 + row) * 32 + c * 4);
        *(uint4*)(Bl + row * FPAD + c * 4) = *(const uint4*)(g_wrl + (size_t)(n0 + row) * 32 + c * 4);
    }
    __syncthreads();

    float4 acc[16];
#pragma unroll
    for (int nb = 0; nb < 16; nb++) acc[nb] = make_float4(0.f, 0.f, 0.f, 0.f);

#pragma unroll
    for (int ks = 0; ks < 4; ks++) {
        const int kb = ks * 8 + q;
        uint32_t ah0 = Ah[(wm + g) * FPAD + kb];
        uint32_t ah1 = Ah[(wm + g + 8) * FPAD + kb];
        uint32_t ah2 = Ah[(wm + g) * FPAD + kb + 4];
        uint32_t ah3 = Ah[(wm + g + 8) * FPAD + kb + 4];
        uint32_t al0 = Al[(wm + g) * FPAD + kb];
        uint32_t al1 = Al[(wm + g + 8) * FPAD + kb];
        uint32_t al2 = Al[(wm + g) * FPAD + kb + 4];
        uint32_t al3 = Al[(wm + g + 8) * FPAD + kb + 4];
#pragma unroll
        for (int nb = 0; nb < 16; nb++) {
            const int n = nb * 8 + g;
            uint32_t bh0 = Bh[n * FPAD + kb];
            uint32_t bh1 = Bh[n * FPAD + kb + 4];
            uint32_t bl0 = Bl[n * FPAD + kb];
            uint32_t bl1 = Bl[n * FPAD + kb + 4];
            mma_bf16(acc[nb], ah0, ah1, ah2, ah3, bh0, bh1);
            mma_bf16(acc[nb], ah0, ah1, ah2, ah3, bl0, bl1);
            mma_bf16(acc[nb], al0, al1, al2, al3, bh0, bh1);
        }
    }

    const int row0 = m0 + wm + g;
#pragma unroll
    for (int nb = 0; nb < 16; nb++) {
        int col = n0 + nb * 8 + 2 * q;
        *(float2*)(out + (size_t)row0 * 1024 + col)       = make_float2(acc[nb].x, acc[nb].y);
        *(float2*)(out + (size_t)(row0 + 8) * 1024 + col) = make_float2(acc[nb].z, acc[nb].w);
    }
}

// ---------------------------------------------------------------------------
extern "C" void kernel_launch(void* const* d_in, const int* in_sizes, int n_in,
                              void* d_out, int out_size) {
    (void)in_sizes; (void)n_in; (void)out_size;
    const float* emb  = (const float*)d_in[0];
    const float* Wq   = (const float*)d_in[1];
    const float* Wk   = (const float*)d_in[2];
    const float* Wv   = (const float*)d_in[3];
    const float* Wout = (const float*)d_in[4];
    float* out = (float*)d_out;

    prep_kernel<<<512, 256>>>(Wq, Wk, Wv, Wout);

    cudaFuncSetAttribute(qkv_fused, cudaFuncAttributeMaxDynamicSharedMemorySize, QKV_SMEM);
    qkv_fused<<<128, 256, QKV_SMEM>>>(emb);

    cudaFuncSetAttribute(flash_mma, cudaFuncAttributeMaxDynamicSharedMemorySize, FL_SMEM);
    flash_mma<<<dim3(64, 4), 128, FL_SMEM>>>();

    combine_kernel<<<Mrows * 32 / 256, 256>>>();

    cudaFuncSetAttribute(outproj_mma, cudaFuncAttributeMaxDynamicSharedMemorySize, OUTP_SMEM);
    outproj_mma<<<dim3(64, 8), 256, OUTP_SMEM>>>(out);
}

// round 6
// speedup vs baseline: 2.5087x; 1.1007x over previous
#include <cuda_runtime.h>
#include <cuda_bf16.h>
#include <cstdint>

#define Bb 4
#define Tt 2048
#define Ee 1024
#define HD 64
#define Mrows (Bb*Tt)
#define FPAD 36   // u32 row stride: 36 % 32 == 4 -> conflict-free fragment reads
#define NSPLIT 4

// scratch (no cudaMalloc allowed)
__device__ __align__(16) uint32_t g_qh[Mrows*32];
__device__ __align__(16) uint32_t g_ql[Mrows*32];
__device__ __align__(16) uint32_t g_kh[Mrows*32];
__device__ __align__(16) uint32_t g_kl[Mrows*32];
__device__ __align__(16) float    g_v [Mrows*HD];
__device__ __align__(16) uint32_t g_vth[Mrows*32];  // V^T tiles: [tile][hd][s2] bf16x2
__device__ __align__(16) uint32_t g_vtl[Mrows*32];
__device__ __align__(16) uint32_t g_wbh[192*512];
__device__ __align__(16) uint32_t g_wbl[192*512];
__device__ __align__(16) uint32_t g_wrh[1024*32];
__device__ __align__(16) uint32_t g_wrl[1024*32];
__device__ __align__(16) uint32_t g_hoh[Mrows*32];
__device__ __align__(16) uint32_t g_hol[Mrows*32];
__device__ __align__(16) float g_po[NSPLIT][Mrows*HD];
__device__ float g_pm[NSPLIT][Mrows];
__device__ float g_pl[NSPLIT][Mrows];

// ---------------------------------------------------------------------------
__device__ __forceinline__ void mma_bf16(float4& c,
                                         uint32_t a0, uint32_t a1, uint32_t a2, uint32_t a3,
                                         uint32_t b0, uint32_t b1) {
    asm volatile(
        "mma.sync.aligned.m16n8k16.row.col.f32.bf16.bf16.f32 "
        "{%0,%1,%2,%3}, {%4,%5,%6,%7}, {%8,%9}, {%0,%1,%2,%3};"
        : "+f"(c.x), "+f"(c.y), "+f"(c.z), "+f"(c.w)
        : "r"(a0), "r"(a1), "r"(a2), "r"(a3), "r"(b0), "r"(b1));
}

__device__ __forceinline__ void bsplit2(float a0, float a1, uint32_t& h, uint32_t& l) {
    __nv_bfloat162 hh = __floats2bfloat162_rn(a0, a1);
    float r0 = a0 - __bfloat162float(hh.x);
    float r1 = a1 - __bfloat162float(hh.y);
    __nv_bfloat162 ll = __floats2bfloat162_rn(r0, r1);
    h = *reinterpret_cast<uint32_t*>(&hh);
    l = *reinterpret_cast<uint32_t*>(&ll);
}

// ---------------------------------------------------------------------------
// Kernel 0: pre-split weights + fold W_out
// ---------------------------------------------------------------------------
__global__ void prep_kernel(const float* __restrict__ Wq, const float* __restrict__ Wk,
                            const float* __restrict__ Wv, const float* __restrict__ Wout) {
    int idx = blockIdx.x * 256 + threadIdx.x;
    if (idx < 98304) {
        int n = idx >> 9, k2 = idx & 511;
        const float* w = (n < 64) ? Wq : ((n < 128) ? Wk : Wv);
        int r = n & 63;
        float a0 = w[(size_t)r * 1024 + 2 * k2];
        float a1 = w[(size_t)r * 1024 + 2 * k2 + 1];
        uint32_t h, l; bsplit2(a0, a1, h, l);
        g_wbh[idx] = h; g_wbl[idx] = l;
    } else {
        int j = idx - 98304;
        int o = j >> 5, d2 = j & 31;
        float s0 = 0.f, s1 = 0.f;
#pragma unroll
        for (int h = 0; h < 16; h++) {
            s0 += Wout[(size_t)o * 1024 + h * 64 + 2 * d2];
            s1 += Wout[(size_t)o * 1024 + h * 64 + 2 * d2 + 1];
        }
        uint32_t h, l; bsplit2(s0, s1, h, l);
        g_wrh[j] = h; g_wrl[j] = l;
    }
}

// ---------------------------------------------------------------------------
// Kernel 1: fused QKV (unchanged from R5)
// ---------------------------------------------------------------------------
#define QKV_SMEM ((64*FPAD*2 + 192*FPAD*2) * 4)

__global__ void __launch_bounds__(256) qkv_fused(const float* __restrict__ emb) {
    extern __shared__ uint32_t smu[];
    uint32_t* Ah = smu;
    uint32_t* Al = Ah + 64 * FPAD;
    uint32_t* Bh = Al + 64 * FPAD;
    uint32_t* Bl = Bh + 192 * FPAD;

    const int m0 = blockIdx.x * 64;
    const int tid = threadIdx.x;
    const int lane = tid & 31;
    const int w = tid >> 5;
    const int wm = (w & 3) * 16;
    const int colbase = (w >> 2) * 96;
    const int g = lane >> 2, q = lane & 3;

    float4 acc[12];
#pragma unroll
    for (int nb = 0; nb < 12; nb++) acc[nb] = make_float4(0.f, 0.f, 0.f, 0.f);

    for (int kt = 0; kt < 16; kt++) {
        __syncthreads();
#pragma unroll
        for (int i = 0; i < 4; i++) {
            int idx = tid + i * 256;
            int row = idx >> 4, c4 = idx & 15;
            float4 v = *(const float4*)(emb + (size_t)(m0 + row) * Ee + kt * 64 + c4 * 4);
            uint32_t h0, l0, h1, l1;
            bsplit2(v.x, v.y, h0, l0);
            bsplit2(v.z, v.w, h1, l1);
            Ah[row * FPAD + c4 * 2] = h0; Ah[row * FPAD + c4 * 2 + 1] = h1;
            Al[row * FPAD + c4 * 2] = l0; Al[row * FPAD + c4 * 2 + 1] = l1;
        }
#pragma unroll
        for (int i = 0; i < 6; i++) {
            int j = tid + i * 256;
            int row = j >> 3, c = j & 7;
            *(uint4*)(Bh + row * FPAD + c * 4) =
                *(const uint4*)(g_wbh + (size_t)row * 512 + kt * 32 + c * 4);
        }
#pragma unroll
        for (int i = 0; i < 6; i++) {
            int j = tid + i * 256;
            int row = j >> 3, c = j & 7;
            *(uint4*)(Bl + row * FPAD + c * 4) =
                *(const uint4*)(g_wbl + (size_t)row * 512 + kt * 32 + c * 4);
        }
        __syncthreads();

#pragma unroll
        for (int ks = 0; ks < 4; ks++) {
            const int kb = ks * 8 + q;
            uint32_t ah0 = Ah[(wm + g) * FPAD + kb];
            uint32_t ah1 = Ah[(wm + g + 8) * FPAD + kb];
            uint32_t ah2 = Ah[(wm + g) * FPAD + kb + 4];
            uint32_t ah3 = Ah[(wm + g + 8) * FPAD + kb + 4];
            uint32_t al0 = Al[(wm + g) * FPAD + kb];
            uint32_t al1 = Al[(wm + g + 8) * FPAD + kb];
            uint32_t al2 = Al[(wm + g) * FPAD + kb + 4];
            uint32_t al3 = Al[(wm + g + 8) * FPAD + kb + 4];
#pragma unroll
            for (int nb = 0; nb < 12; nb++) {
                const int n = colbase + nb * 8 + g;
                uint32_t bh0 = Bh[n * FPAD + kb];
                uint32_t bh1 = Bh[n * FPAD + kb + 4];
                uint32_t bl0 = Bl[n * FPAD + kb];
                uint32_t bl1 = Bl[n * FPAD + kb + 4];
                mma_bf16(acc[nb], ah0, ah1, ah2, ah3, bh0, bh1);
                mma_bf16(acc[nb], ah0, ah1, ah2, ah3, bl0, bl1);
                mma_bf16(acc[nb], al0, al1, al2, al3, bh0, bh1);
            }
        }
    }

    const size_t r0 = m0 + wm + g;
#pragma unroll
    for (int nb = 0; nb < 12; nb++) {
        int gcol = colbase + nb * 8 + 2 * q;
        int sec = gcol >> 6;
        int lc = gcol & 63;
        float4 c = acc[nb];
        if (sec == 0) {
            uint32_t h, l;
            bsplit2(c.x * 0.125f, c.y * 0.125f, h, l);
            g_qh[r0 * 32 + lc / 2] = h; g_ql[r0 * 32 + lc / 2] = l;
            bsplit2(c.z * 0.125f, c.w * 0.125f, h, l);
            g_qh[(r0 + 8) * 32 + lc / 2] = h; g_ql[(r0 + 8) * 32 + lc / 2] = l;
        } else if (sec == 1) {
            uint32_t h, l;
            bsplit2(c.x, c.y, h, l);
            g_kh[r0 * 32 + lc / 2] = h; g_kl[r0 * 32 + lc / 2] = l;
            bsplit2(c.z, c.w, h, l);
            g_kh[(r0 + 8) * 32 + lc / 2] = h; g_kl[(r0 + 8) * 32 + lc / 2] = l;
        } else {
            *(float2*)(g_v + r0 * HD + lc)       = make_float2(c.x, c.y);
            *(float2*)(g_v + (r0 + 8) * HD + lc) = make_float2(c.z, c.w);
        }
    }
}

// ---------------------------------------------------------------------------
// Kernel 1b: V -> transposed bf16 hi/lo tiles [tile][hd][s2]
// ---------------------------------------------------------------------------
__global__ void vsplit_kernel() {
    int idx = blockIdx.x * 256 + threadIdx.x;   // Mrows*32 = tile*2048 + hd*32 + s2
    int s2 = idx & 31;
    int hd = (idx >> 5) & 63;
    int tile = idx >> 11;
    float v0 = g_v[((size_t)tile * 64 + 2 * s2) * 64 + hd];
    float v1 = g_v[((size_t)tile * 64 + 2 * s2 + 1) * 64 + hd];
    uint32_t h, l; bsplit2(v0, v1, h, l);
    g_vth[idx] = h;
    g_vtl[idx] = l;
}

// ---------------------------------------------------------------------------
// Kernel 2: flash attention, 3xBF16, split-KV 4-way.
// grid (128, 4): blockIdx.x = (31-qt)*4 + part. block 128 (4 warps x 16 rows).
// smem u32: Kh Kl Vth Vtl Ph Pl each [64*36]
// ---------------------------------------------------------------------------
#define FL_SMEM (6 * 64 * FPAD * 4)

__global__ void __launch_bounds__(128) flash_mma() {
    extern __shared__ uint32_t smu[];
    uint32_t* Kh  = smu;
    uint32_t* Kl  = Kh  + 64 * FPAD;
    uint32_t* Vth = Kl  + 64 * FPAD;
    uint32_t* Vtl = Vth + 64 * FPAD;
    uint32_t* Ph  = Vtl + 64 * FPAD;
    uint32_t* Pl  = Ph  + 64 * FPAD;

    const int b = blockIdx.y;
    const int qt = 31 - (blockIdx.x >> 2);
    const int part = blockIdx.x & 3;
    const int q0 = qt * 64;
    const int tid = threadIdx.x;
    const int lane = tid & 31;
    const int wm = (tid >> 5) * 16;
    const int g = lane >> 2, q = lane & 3;

    const int nt = qt + 1;
    const int t_begin = (part * nt) >> 2;
    const int t_end = ((part + 1) * nt) >> 2;

    const size_t qrow0 = (size_t)b * Tt + q0;
    uint32_t qh[4][4], ql[4][4];
#pragma unroll
    for (int ks = 0; ks < 4; ks++) {
        const int kb = ks * 8 + q;
        qh[ks][0] = g_qh[(qrow0 + wm + g) * 32 + kb];
        qh[ks][1] = g_qh[(qrow0 + wm + g + 8) * 32 + kb];
        qh[ks][2] = g_qh[(qrow0 + wm + g) * 32 + kb + 4];
        qh[ks][3] = g_qh[(qrow0 + wm + g + 8) * 32 + kb + 4];
        ql[ks][0] = g_ql[(qrow0 + wm + g) * 32 + kb];
        ql[ks][1] = g_ql[(qrow0 + wm + g + 8) * 32 + kb];
        ql[ks][2] = g_ql[(qrow0 + wm + g) * 32 + kb + 4];
        ql[ks][3] = g_ql[(qrow0 + wm + g + 8) * 32 + kb + 4];
    }

    float m0r = -1e30f, m1r = -1e30f, l0r = 0.f, l1r = 0.f;
    float4 o[8];
#pragma unroll
    for (int nb = 0; nb < 8; nb++) o[nb] = make_float4(0.f, 0.f, 0.f, 0.f);

    for (int t = t_begin; t < t_end; t++) {
        const int k0 = t * 64;
        __syncthreads();
        {
            const size_t base = ((size_t)b * Tt + k0) * 32;
            const uint4* sh = (const uint4*)(g_kh + base);
            const uint4* sl = (const uint4*)(g_kl + base);
            const uint4* vh = (const uint4*)(g_vth + base);
            const uint4* vl = (const uint4*)(g_vtl + base);
#pragma unroll
            for (int i = 0; i < 4; i++) {
                int idx = tid + i * 128;
                int row = idx >> 3, c = idx & 7;
                *(uint4*)(Kh  + row * FPAD + c * 4) = sh[idx];
                *(uint4*)(Kl  + row * FPAD + c * 4) = sl[idx];
                *(uint4*)(Vth + row * FPAD + c * 4) = vh[idx];
                *(uint4*)(Vtl + row * FPAD + c * 4) = vl[idx];
            }
        }
        __syncthreads();

        // S = Q K^T
        float4 s[8];
#pragma unroll
        for (int nb = 0; nb < 8; nb++) s[nb] = make_float4(0.f, 0.f, 0.f, 0.f);
#pragma unroll
        for (int ks = 0; ks < 4; ks++) {
            const int kb = ks * 8 + q;
#pragma unroll
            for (int nb = 0; nb < 8; nb++) {
                const int n = nb * 8 + g;
                uint32_t bh0 = Kh[n * FPAD + kb];
                uint32_t bh1 = Kh[n * FPAD + kb + 4];
                uint32_t bl0 = Kl[n * FPAD + kb];
                uint32_t bl1 = Kl[n * FPAD + kb + 4];
                mma_bf16(s[nb], qh[ks][0], qh[ks][1], qh[ks][2], qh[ks][3], bh0, bh1);
                mma_bf16(s[nb], qh[ks][0], qh[ks][1], qh[ks][2], qh[ks][3], bl0, bl1);
                mma_bf16(s[nb], ql[ks][0], ql[ks][1], ql[ks][2], ql[ks][3], bh0, bh1);
            }
        }

        if (k0 == q0) {
            const int r0g = q0 + wm + g;
#pragma unroll
            for (int nb = 0; nb < 8; nb++) {
                int c = k0 + nb * 8 + 2 * q;
                if (c > r0g)         s[nb].x = -1e30f;
                if (c + 1 > r0g)     s[nb].y = -1e30f;
                if (c > r0g + 8)     s[nb].z = -1e30f;
                if (c + 1 > r0g + 8) s[nb].w = -1e30f;
            }
        }

        float mx0 = -1e30f, mx1 = -1e30f;
#pragma unroll
        for (int nb = 0; nb < 8; nb++) {
            mx0 = fmaxf(mx0, fmaxf(s[nb].x, s[nb].y));
            mx1 = fmaxf(mx1, fmaxf(s[nb].z, s[nb].w));
        }
        mx0 = fmaxf(mx0, __shfl_xor_sync(0xffffffffu, mx0, 1));
        mx0 = fmaxf(mx0, __shfl_xor_sync(0xffffffffu, mx0, 2));
        mx1 = fmaxf(mx1, __shfl_xor_sync(0xffffffffu, mx1, 1));
        mx1 = fmaxf(mx1, __shfl_xor_sync(0xffffffffu, mx1, 2));
        float mn0 = fmaxf(m0r, mx0), mn1 = fmaxf(m1r, mx1);
        float a0 = __expf(m0r - mn0), a1 = __expf(m1r - mn1);
        m0r = mn0; m1r = mn1;

        float rs0 = 0.f, rs1 = 0.f;
#pragma unroll
        for (int nb = 0; nb < 8; nb++) {
            float p0 = __expf(s[nb].x - mn0);
            float p1 = __expf(s[nb].y - mn0);
            float p2 = __expf(s[nb].z - mn1);
            float p3 = __expf(s[nb].w - mn1);
            rs0 += p0 + p1;
            rs1 += p2 + p3;
            uint32_t h, l;
            bsplit2(p0, p1, h, l);
            Ph[(wm + g) * FPAD + nb * 4 + q] = h;
            Pl[(wm + g) * FPAD + nb * 4 + q] = l;
            bsplit2(p2, p3, h, l);
            Ph[(wm + g + 8) * FPAD + nb * 4 + q] = h;
            Pl[(wm + g + 8) * FPAD + nb * 4 + q] = l;
        }
        rs0 += __shfl_xor_sync(0xffffffffu, rs0, 1);
        rs0 += __shfl_xor_sync(0xffffffffu, rs0, 2);
        rs1 += __shfl_xor_sync(0xffffffffu, rs1, 1);
        rs1 += __shfl_xor_sync(0xffffffffu, rs1, 2);
        l0r = l0r * a0 + rs0;
        l1r = l1r * a1 + rs1;
#pragma unroll
        for (int nb = 0; nb < 8; nb++) {
            o[nb].x *= a0; o[nb].y *= a0;
            o[nb].z *= a1; o[nb].w *= a1;
        }
        __syncwarp();

        // O += P V
#pragma unroll
        for (int ks = 0; ks < 4; ks++) {
            const int kb = ks * 8 + q;
            uint32_t ph0 = Ph[(wm + g) * FPAD + kb];
            uint32_t ph1 = Ph[(wm + g + 8) * FPAD + kb];
            uint32_t ph2 = Ph[(wm + g) * FPAD + kb + 4];
            uint32_t ph3 = Ph[(wm + g + 8) * FPAD + kb + 4];
            uint32_t pl0 = Pl[(wm + g) * FPAD + kb];
            uint32_t pl1 = Pl[(wm + g + 8) * FPAD + kb];
            uint32_t pl2 = Pl[(wm + g) * FPAD + kb + 4];
            uint32_t pl3 = Pl[(wm + g + 8) * FPAD + kb + 4];
#pragma unroll
            for (int nb = 0; nb < 8; nb++) {
                const int n = nb * 8 + g;
                uint32_t vh0 = Vth[n * FPAD + kb];
                uint32_t vh1 = Vth[n * FPAD + kb + 4];
                uint32_t vl0 = Vtl[n * FPAD + kb];
                uint32_t vl1 = Vtl[n * FPAD + kb + 4];
                mma_bf16(o[nb], ph0, ph1, ph2, ph3, vh0, vh1);
                mma_bf16(o[nb], ph0, ph1, ph2, ph3, vl0, vl1);
                mma_bf16(o[nb], pl0, pl1, pl2, pl3, vh0, vh1);
            }
        }
    }

    const size_t row0 = (size_t)b * Tt + q0 + wm + g;
    float* po = g_po[part];
#pragma unroll
    for (int nb = 0; nb < 8; nb++) {
        int col = nb * 8 + 2 * q;
        *(float2*)(po + row0 * HD + col)       = make_float2(o[nb].x, o[nb].y);
        *(float2*)(po + (row0 + 8) * HD + col) = make_float2(o[nb].z, o[nb].w);
    }
    if (q == 0) {
        g_pm[part][row0] = m0r;     g_pl[part][row0] = l0r;
        g_pm[part][row0 + 8] = m1r; g_pl[part][row0 + 8] = l1r;
    }
}

// ---------------------------------------------------------------------------
// Kernel 3: combine 4 split-KV partials -> pre-split bf16 HO
// ---------------------------------------------------------------------------
__global__ void combine_kernel() {
    int idx = blockIdx.x * 256 + threadIdx.x;   // Mrows*32
    int row = idx >> 5;
    int d2 = idx & 31;
    float mx = -1e30f;
#pragma unroll
    for (int p = 0; p < NSPLIT; p++) mx = fmaxf(mx, g_pm[p][row]);
    float wgt[NSPLIT];
    float l = 0.f;
#pragma unroll
    for (int p = 0; p < NSPLIT; p++) {
        wgt[p] = __expf(g_pm[p][row] - mx);
        l += g_pl[p][row] * wgt[p];
    }
    float inv = 1.f / l;
    float o0 = 0.f, o1 = 0.f;
#pragma unroll
    for (int p = 0; p < NSPLIT; p++) {
        float2 a = *(const float2*)(g_po[p] + (size_t)row * HD + 2 * d2);
        o0 += a.x * wgt[p];
        o1 += a.y * wgt[p];
    }
    o0 *= inv; o1 *= inv;
    uint32_t h, lo; bsplit2(o0, o1, h, lo);
    g_hoh[idx] = h; g_hol[idx] = lo;
}

// ---------------------------------------------------------------------------
// Kernel 4: out-proj 3xBF16. CTA 128x256, block 512 (16 warps: 8m x 2n).
// grid (64, 4) = 256 CTAs -> single wave at 2 CTAs/SM (110KB smem).
// ---------------------------------------------------------------------------
#define OUTP_SMEM ((2*128*FPAD + 2*256*FPAD) * 4)

__global__ void __launch_bounds__(512) outproj_mma(float* __restrict__ out) {
    extern __shared__ uint32_t smu[];
    uint32_t* Ah = smu;
    uint32_t* Al = Ah + 128 * FPAD;
    uint32_t* Bh = Al + 128 * FPAD;
    uint32_t* Bl = Bh + 256 * FPAD;

    const int m0 = blockIdx.x * 128, n0 = blockIdx.y * 256;
    const int tid = threadIdx.x;
    const int lane = tid & 31;
    const int w = tid >> 5;
    const int wm = (w & 7) * 16;
    const int ncb = (w >> 3) * 128;
    const int g = lane >> 2, q = lane & 3;

    // A: 128 rows x 8 uint4 = 1024 -> 2/thread; B: 256 rows x 8 = 2048 -> 4/thread
#pragma unroll
    for (int i = 0; i < 2; i++) {
        int j = tid + i * 512;
        int row = j >> 3, c = j & 7;
        *(uint4*)(Ah + row * FPAD + c * 4) = *(const uint4*)(g_hoh + (size_t)(m0 + row) * 32 + c * 4);
        *(uint4*)(Al + row * FPAD + c * 4) = *(const uint4*)(g_hol + (size_t)(m0 + row) * 32 + c * 4);
    }
#pragma unroll
    for (int i = 0; i < 4; i++) {
        int j = tid + i * 512;
        int row = j >> 3, c = j & 7;
        *(uint4*)(Bh + row * FPAD + c * 4) = *(const uint4*)(g_wrh + (size_t)(n0 + row) * 32 + c * 4);
        *(uint4*)(Bl + row * FPAD + c * 4) = *(const uint4*)(g_wrl + (size_t)(n0 + row) * 32 + c * 4);
    }
    __syncthreads();

    float4 acc[16];
#pragma unroll
    for (int nb = 0; nb < 16; nb++) acc[nb] = make_float4(0.f, 0.f, 0.f, 0.f);

#pragma unroll
    for (int ks = 0; ks < 4; ks++) {
        const int kb = ks * 8 + q;
        uint32_t ah0 = Ah[(wm + g) * FPAD + kb];
        uint32_t ah1 = Ah[(wm + g + 8) * FPAD + kb];
        uint32_t ah2 = Ah[(wm + g) * FPAD + kb + 4];
        uint32_t ah3 = Ah[(wm + g + 8) * FPAD + kb + 4];
        uint32_t al0 = Al[(wm + g) * FPAD + kb];
        uint32_t al1 = Al[(wm + g + 8) * FPAD + kb];
        uint32_t al2 = Al[(wm + g) * FPAD + kb + 4];
        uint32_t al3 = Al[(wm + g + 8) * FPAD + kb + 4];
#pragma unroll
        for (int nb = 0; nb < 16; nb++) {
            const int n = ncb + nb * 8 + g;
            uint32_t bh0 = Bh[n * FPAD + kb];
            uint32_t bh1 = Bh[n * FPAD + kb + 4];
            uint32_t bl0 = Bl[n * FPAD + kb];
            uint32_t bl1 = Bl[n * FPAD + kb + 4];
            mma_bf16(acc[nb], ah0, ah1, ah2, ah3, bh0, bh1);
            mma_bf16(acc[nb], ah0, ah1, ah2, ah3, bl0, bl1);
            mma_bf16(acc[nb], al0, al1, al2, al3, bh0, bh1);
        }
    }

    const int row0 = m0 + wm + g;
#pragma unroll
    for (int nb = 0; nb < 16; nb++) {
        int col = n0 + ncb + nb * 8 + 2 * q;
        *(float2*)(out + (size_t)row0 * 1024 + col)       = make_float2(acc[nb].x, acc[nb].y);
        *(float2*)(out + (size_t)(row0 + 8) * 1024 + col) = make_float2(acc[nb].z, acc[nb].w);
    }
}

// ---------------------------------------------------------------------------
extern "C" void kernel_launch(void* const* d_in, const int* in_sizes, int n_in,
                              void* d_out, int out_size) {
    (void)in_sizes; (void)n_in; (void)out_size;
    const float* emb  = (const float*)d_in[0];
    const float* Wq   = (const float*)d_in[1];
    const float* Wk   = (const float*)d_in[2];
    const float* Wv   = (const float*)d_in[3];
    const float* Wout = (const float*)d_in[4];
    float* out = (float*)d_out;

    prep_kernel<<<512, 256>>>(Wq, Wk, Wv, Wout);

    cudaFuncSetAttribute(qkv_fused, cudaFuncAttributeMaxDynamicSharedMemorySize, QKV_SMEM);
    qkv_fused<<<128, 256, QKV_SMEM>>>(emb);

    vsplit_kernel<<<Mrows * 32 / 256, 256>>>();

    cudaFuncSetAttribute(flash_mma, cudaFuncAttributeMaxDynamicSharedMemorySize, FL_SMEM);
    flash_mma<<<dim3(128, 4), 128, FL_SMEM>>>();

    combine_kernel<<<Mrows * 32 / 256, 256>>>();

    cudaFuncSetAttribute(outproj_mma, cudaFuncAttributeMaxDynamicSharedMemorySize, OUTP_SMEM);
    outproj_mma<<<dim3(64, 4), 512, OUTP_SMEM>>>(out);
}

// round 7
// speedup vs baseline: 2.8944x; 1.1538x over previous
#include <cuda_runtime.h>
#include <cuda_bf16.h>
#include <cstdint>

#define Bb 4
#define Tt 2048
#define Ee 1024
#define HD 64
#define Mrows (Bb*Tt)
#define FPAD 36   // u32 row stride: 36 % 32 == 4 -> conflict-free fragment reads
#define NSPLIT 4

// scratch (no cudaMalloc allowed)
__device__ __align__(16) uint32_t g_qh[Mrows*32];
__device__ __align__(16) uint32_t g_ql[Mrows*32];
__device__ __align__(16) uint32_t g_kh[Mrows*32];
__device__ __align__(16) uint32_t g_kl[Mrows*32];
__device__ __align__(16) float    g_v [Mrows*HD];
__device__ __align__(16) uint32_t g_vth[Mrows*32];  // V^T tiles: [tile][hd][s2] bf16x2
__device__ __align__(16) uint32_t g_vtl[Mrows*32];
__device__ __align__(16) uint32_t g_wbh[192*512];
__device__ __align__(16) uint32_t g_wbl[192*512];
__device__ __align__(16) uint32_t g_wrh[1024*32];
__device__ __align__(16) uint32_t g_wrl[1024*32];
__device__ __align__(16) uint32_t g_hoh[Mrows*32];
__device__ __align__(16) uint32_t g_hol[Mrows*32];
__device__ __align__(16) float g_po[NSPLIT][Mrows*HD];
__device__ float g_pm[NSPLIT][Mrows];
__device__ float g_pl[NSPLIT][Mrows];

// ---------------------------------------------------------------------------
__device__ __forceinline__ void mma_bf16(float4& c,
                                         uint32_t a0, uint32_t a1, uint32_t a2, uint32_t a3,
                                         uint32_t b0, uint32_t b1) {
    asm volatile(
        "mma.sync.aligned.m16n8k16.row.col.f32.bf16.bf16.f32 "
        "{%0,%1,%2,%3}, {%4,%5,%6,%7}, {%8,%9}, {%0,%1,%2,%3};"
        : "+f"(c.x), "+f"(c.y), "+f"(c.z), "+f"(c.w)
        : "r"(a0), "r"(a1), "r"(a2), "r"(a3), "r"(b0), "r"(b1));
}

__device__ __forceinline__ void bsplit2(float a0, float a1, uint32_t& h, uint32_t& l) {
    __nv_bfloat162 hh = __floats2bfloat162_rn(a0, a1);
    float r0 = a0 - __bfloat162float(hh.x);
    float r1 = a1 - __bfloat162float(hh.y);
    __nv_bfloat162 ll = __floats2bfloat162_rn(r0, r1);
    h = *reinterpret_cast<uint32_t*>(&hh);
    l = *reinterpret_cast<uint32_t*>(&ll);
}

__device__ __forceinline__ void cp16(uint32_t dst, const void* src) {
    asm volatile("cp.async.cg.shared.global [%0], [%1], 16;" :: "r"(dst), "l"(src));
}
__device__ __forceinline__ void cp_commit() {
    asm volatile("cp.async.commit_group;");
}
__device__ __forceinline__ void cp_wait0() {
    asm volatile("cp.async.wait_group 0;");
}

// ---------------------------------------------------------------------------
// Kernel 0: pre-split weights + fold W_out
// ---------------------------------------------------------------------------
__global__ void prep_kernel(const float* __restrict__ Wq, const float* __restrict__ Wk,
                            const float* __restrict__ Wv, const float* __restrict__ Wout) {
    int idx = blockIdx.x * 256 + threadIdx.x;
    if (idx < 98304) {
        int n = idx >> 9, k2 = idx & 511;
        const float* w = (n < 64) ? Wq : ((n < 128) ? Wk : Wv);
        int r = n & 63;
        float a0 = w[(size_t)r * 1024 + 2 * k2];
        float a1 = w[(size_t)r * 1024 + 2 * k2 + 1];
        uint32_t h, l; bsplit2(a0, a1, h, l);
        g_wbh[idx] = h; g_wbl[idx] = l;
    } else {
        int j = idx - 98304;
        int o = j >> 5, d2 = j & 31;
        float s0 = 0.f, s1 = 0.f;
#pragma unroll
        for (int h = 0; h < 16; h++) {
            s0 += Wout[(size_t)o * 1024 + h * 64 + 2 * d2];
            s1 += Wout[(size_t)o * 1024 + h * 64 + 2 * d2 + 1];
        }
        uint32_t h, l; bsplit2(s0, s1, h, l);
        g_wrh[j] = h; g_wrl[j] = l;
    }
}

// ---------------------------------------------------------------------------
// Kernel 1: fused QKV, block 512 (16 warps = 4m x 4col, warp 16r x 48c).
// B double-buffered via cp.async; A register-prefetched then bsplit->smem.
// smem u32: A: 2buf x (Ah,Al)[64*36]; B: 2buf x (Bh,Bl)[192*36]  -> 147456 B
// ---------------------------------------------------------------------------
#define QKV_ABUF (2*64*FPAD)            // u32 per A buffer (Ah+Al)
#define QKV_BBUF (2*192*FPAD)           // u32 per B buffer (Bh+Bl)
#define QKV_B0   (2*QKV_ABUF)           // B region starts after 2 A buffers
#define QKV_SMEM ((2*QKV_ABUF + 2*QKV_BBUF) * 4)

__global__ void __launch_bounds__(512) qkv_fused(const float* __restrict__ emb) {
    extern __shared__ uint32_t smu[];
    const uint32_t sb = (uint32_t)__cvta_generic_to_shared(smu);

    const int m0 = blockIdx.x * 64;
    const int tid = threadIdx.x;
    const int lane = tid & 31;
    const int w = tid >> 5;
    const int wm = (w & 3) * 16;
    const int colbase = (w >> 2) * 48;
    const int g = lane >> 2, q = lane & 3;

    float4 acc[6];
#pragma unroll
    for (int nb = 0; nb < 6; nb++) acc[nb] = make_float4(0.f, 0.f, 0.f, 0.f);

    // A LDG mapping: 2 float4/thread
    const int arow0 = tid >> 4,            ac0 = tid & 15;
    const int arow1 = (tid + 512) >> 4,    ac1 = (tid + 512) & 15;

    // prologue: A(0) -> regs, B(0) -> cp.async buf0
    float4 aR0 = *(const float4*)(emb + (size_t)(m0 + arow0) * Ee + 0 + ac0 * 4);
    float4 aR1 = *(const float4*)(emb + (size_t)(m0 + arow1) * Ee + 0 + ac1 * 4);
#pragma unroll
    for (int i = 0; i < 6; i++) {
        const uint32_t* gp = (i < 3) ? g_wbh : g_wbl;
        int rem = tid + (i % 3) * 512;
        int row = rem >> 3, c = rem & 7;
        uint32_t dst = sb + (QKV_B0 + (i < 3 ? 0 : 192 * FPAD) + row * FPAD + c * 4) * 4;
        cp16(dst, gp + (size_t)row * 512 + 0 * 32 + c * 4);
    }
    cp_commit();

    for (int kt = 0; kt < 16; kt++) {
        const int buf = kt & 1;
        uint32_t* Ah = smu + buf * QKV_ABUF;
        uint32_t* Al = Ah + 64 * FPAD;
        uint32_t* Bh = smu + QKV_B0 + buf * QKV_BBUF;
        uint32_t* Bl = Bh + 192 * FPAD;

        // store prefetched A regs into this buffer
        {
            uint32_t h0, l0, h1, l1;
            bsplit2(aR0.x, aR0.y, h0, l0);
            bsplit2(aR0.z, aR0.w, h1, l1);
            Ah[arow0 * FPAD + ac0 * 2] = h0; Ah[arow0 * FPAD + ac0 * 2 + 1] = h1;
            Al[arow0 * FPAD + ac0 * 2] = l0; Al[arow0 * FPAD + ac0 * 2 + 1] = l1;
            bsplit2(aR1.x, aR1.y, h0, l0);
            bsplit2(aR1.z, aR1.w, h1, l1);
            Ah[arow1 * FPAD + ac1 * 2] = h0; Ah[arow1 * FPAD + ac1 * 2 + 1] = h1;
            Al[arow1 * FPAD + ac1 * 2] = l0; Al[arow1 * FPAD + ac1 * 2 + 1] = l1;
        }
        cp_wait0();
        __syncthreads();

        if (kt < 15) {
            const int kn = (kt + 1) * 64;
            aR0 = *(const float4*)(emb + (size_t)(m0 + arow0) * Ee + kn + ac0 * 4);
            aR1 = *(const float4*)(emb + (size_t)(m0 + arow1) * Ee + kn + ac1 * 4);
            const int nbuf = buf ^ 1;
#pragma unroll
            for (int i = 0; i < 6; i++) {
                const uint32_t* gp = (i < 3) ? g_wbh : g_wbl;
                int rem = tid + (i % 3) * 512;
                int row = rem >> 3, c = rem & 7;
                uint32_t dst = sb + (QKV_B0 + nbuf * QKV_BBUF
                                     + (i < 3 ? 0 : 192 * FPAD) + row * FPAD + c * 4) * 4;
                cp16(dst, gp + (size_t)row * 512 + (kt + 1) * 32 + c * 4);
            }
            cp_commit();
        }

#pragma unroll
        for (int ks = 0; ks < 4; ks++) {
            const int kb = ks * 8 + q;
            uint32_t ah0 = Ah[(wm + g) * FPAD + kb];
            uint32_t ah1 = Ah[(wm + g + 8) * FPAD + kb];
            uint32_t ah2 = Ah[(wm + g) * FPAD + kb + 4];
            uint32_t ah3 = Ah[(wm + g + 8) * FPAD + kb + 4];
            uint32_t al0 = Al[(wm + g) * FPAD + kb];
            uint32_t al1 = Al[(wm + g + 8) * FPAD + kb];
            uint32_t al2 = Al[(wm + g) * FPAD + kb + 4];
            uint32_t al3 = Al[(wm + g + 8) * FPAD + kb + 4];
#pragma unroll
            for (int nb = 0; nb < 6; nb++) {
                const int n = colbase + nb * 8 + g;
                uint32_t bh0 = Bh[n * FPAD + kb];
                uint32_t bh1 = Bh[n * FPAD + kb + 4];
                uint32_t bl0 = Bl[n * FPAD + kb];
                uint32_t bl1 = Bl[n * FPAD + kb + 4];
                mma_bf16(acc[nb], ah0, ah1, ah2, ah3, bh0, bh1);
                mma_bf16(acc[nb], ah0, ah1, ah2, ah3, bl0, bl1);
                mma_bf16(acc[nb], al0, al1, al2, al3, bh0, bh1);
            }
        }
        __syncthreads();
    }

    const size_t r0 = m0 + wm + g;
#pragma unroll
    for (int nb = 0; nb < 6; nb++) {
        int gcol = colbase + nb * 8 + 2 * q;
        int sec = gcol >> 6;
        int lc = gcol & 63;
        float4 c = acc[nb];
        if (sec == 0) {
            uint32_t h, l;
            bsplit2(c.x * 0.125f, c.y * 0.125f, h, l);
            g_qh[r0 * 32 + lc / 2] = h; g_ql[r0 * 32 + lc / 2] = l;
            bsplit2(c.z * 0.125f, c.w * 0.125f, h, l);
            g_qh[(r0 + 8) * 32 + lc / 2] = h; g_ql[(r0 + 8) * 32 + lc / 2] = l;
        } else if (sec == 1) {
            uint32_t h, l;
            bsplit2(c.x, c.y, h, l);
            g_kh[r0 * 32 + lc / 2] = h; g_kl[r0 * 32 + lc / 2] = l;
            bsplit2(c.z, c.w, h, l);
            g_kh[(r0 + 8) * 32 + lc / 2] = h; g_kl[(r0 + 8) * 32 + lc / 2] = l;
        } else {
            *(float2*)(g_v + r0 * HD + lc)       = make_float2(c.x, c.y);
            *(float2*)(g_v + (r0 + 8) * HD + lc) = make_float2(c.z, c.w);
        }
    }
}

// ---------------------------------------------------------------------------
// Kernel 1b: V -> transposed bf16 hi/lo tiles [tile][hd][s2]
// ---------------------------------------------------------------------------
__global__ void vsplit_kernel() {
    int idx = blockIdx.x * 256 + threadIdx.x;
    int s2 = idx & 31;
    int hd = (idx >> 5) & 63;
    int tile = idx >> 11;
    float v0 = g_v[((size_t)tile * 64 + 2 * s2) * 64 + hd];
    float v1 = g_v[((size_t)tile * 64 + 2 * s2 + 1) * 64 + hd];
    uint32_t h, l; bsplit2(v0, v1, h, l);
    g_vth[idx] = h;
    g_vtl[idx] = l;
}

// ---------------------------------------------------------------------------
// Kernel 2: flash attention, 3xBF16, BQ=128 (8 warps), split-KV 4-way,
// cp.async double-buffered K/V. grid (64, 4): x = (15-qt)*4 + part.
// smem u32: 2 bufs x (Kh,Kl,Vth,Vtl)[64*36] + (Ph,Pl)[128*36] = 110592 B
// ---------------------------------------------------------------------------
#define FL_KVBUF (4*64*FPAD)              // u32 per KV buffer
#define FL_P0    (2*FL_KVBUF)
#define FL_SMEM  ((2*FL_KVBUF + 2*128*FPAD) * 4)

__device__ __forceinline__ void fl_prefetch(uint32_t sb, int bufoff, size_t gbase, int tid) {
#pragma unroll
    for (int i = 0; i < 8; i++) {
        const uint32_t* gp = (i < 2) ? g_kh : (i < 4) ? g_kl : (i < 6) ? g_vth : g_vtl;
        int rem = tid + (i & 1) * 256;
        int row = rem >> 3, c = rem & 7;
        uint32_t dst = sb + (bufoff + (i >> 1) * (64 * FPAD) + row * FPAD + c * 4) * 4;
        cp16(dst, gp + gbase + rem * 4);
    }
}

__global__ void __launch_bounds__(256, 2) flash_mma() {
    extern __shared__ uint32_t smu[];
    const uint32_t sb = (uint32_t)__cvta_generic_to_shared(smu);
    uint32_t* Ph = smu + FL_P0;
    uint32_t* Pl = Ph + 128 * FPAD;

    const int b = blockIdx.y;
    const int qt = 15 - (blockIdx.x >> 2);
    const int part = blockIdx.x & 3;
    const int q0 = qt * 128;
    const int tid = threadIdx.x;
    const int lane = tid & 31;
    const int wm = (tid >> 5) * 16;
    const int g = lane >> 2, q = lane & 3;

    const int nt = 2 * qt + 2;
    const int t_begin = (part * nt) >> 2;
    const int t_end = ((part + 1) * nt) >> 2;

    // Q fragments from pre-split gmem
    const size_t qrow0 = (size_t)b * Tt + q0;
    uint32_t qh[4][4], ql[4][4];
#pragma unroll
    for (int ks = 0; ks < 4; ks++) {
        const int kb = ks * 8 + q;
        qh[ks][0] = g_qh[(qrow0 + wm + g) * 32 + kb];
        qh[ks][1] = g_qh[(qrow0 + wm + g + 8) * 32 + kb];
        qh[ks][2] = g_qh[(qrow0 + wm + g) * 32 + kb + 4];
        qh[ks][3] = g_qh[(qrow0 + wm + g + 8) * 32 + kb + 4];
        ql[ks][0] = g_ql[(qrow0 + wm + g) * 32 + kb];
        ql[ks][1] = g_ql[(qrow0 + wm + g + 8) * 32 + kb];
        ql[ks][2] = g_ql[(qrow0 + wm + g) * 32 + kb + 4];
        ql[ks][3] = g_ql[(qrow0 + wm + g + 8) * 32 + kb + 4];
    }

    float m0r = -1e30f, m1r = -1e30f, l0r = 0.f, l1r = 0.f;
    float4 o[8];
#pragma unroll
    for (int nb = 0; nb < 8; nb++) o[nb] = make_float4(0.f, 0.f, 0.f, 0.f);

    if (t_begin < t_end) {
        fl_prefetch(sb, 0, ((size_t)b * Tt + t_begin * 64) * 32, tid);
        cp_commit();
    }

    int buf = 0;
    for (int t = t_begin; t < t_end; t++) {
        const int k0 = t * 64;
        cp_wait0();
        __syncthreads();
        if (t + 1 < t_end) {
            fl_prefetch(sb, (buf ^ 1) * FL_KVBUF, ((size_t)b * Tt + (t + 1) * 64) * 32, tid);
            cp_commit();
        }
        uint32_t* Kh  = smu + buf * FL_KVBUF;
        uint32_t* Kl  = Kh + 64 * FPAD;
        uint32_t* Vth = Kh + 2 * 64 * FPAD;
        uint32_t* Vtl = Kh + 3 * 64 * FPAD;

        // S = Q K^T
        float4 s[8];
#pragma unroll
        for (int nb = 0; nb < 8; nb++) s[nb] = make_float4(0.f, 0.f, 0.f, 0.f);
#pragma unroll
        for (int ks = 0; ks < 4; ks++) {
            const int kb = ks * 8 + q;
#pragma unroll
            for (int nb = 0; nb < 8; nb++) {
                const int n = nb * 8 + g;
                uint32_t bh0 = Kh[n * FPAD + kb];
                uint32_t bh1 = Kh[n * FPAD + kb + 4];
                uint32_t bl0 = Kl[n * FPAD + kb];
                uint32_t bl1 = Kl[n * FPAD + kb + 4];
                mma_bf16(s[nb], qh[ks][0], qh[ks][1], qh[ks][2], qh[ks][3], bh0, bh1);
                mma_bf16(s[nb], qh[ks][0], qh[ks][1], qh[ks][2], qh[ks][3], bl0, bl1);
                mma_bf16(s[nb], ql[ks][0], ql[ks][1], ql[ks][2], ql[ks][3], bh0, bh1);
            }
        }

        // causal mask; -3e30 so fully-masked rows yield p = exp(-2e30) = 0
        if (k0 + 63 > q0 + wm) {
            const int r0g = q0 + wm + g;
#pragma unroll
            for (int nb = 0; nb < 8; nb++) {
                int c = k0 + nb * 8 + 2 * q;
                if (c > r0g)         s[nb].x = -3e30f;
                if (c + 1 > r0g)     s[nb].y = -3e30f;
                if (c > r0g + 8)     s[nb].z = -3e30f;
                if (c + 1 > r0g + 8) s[nb].w = -3e30f;
            }
        }

        float mx0 = -3e30f, mx1 = -3e30f;
#pragma unroll
        for (int nb = 0; nb < 8; nb++) {
            mx0 = fmaxf(mx0, fmaxf(s[nb].x, s[nb].y));
            mx1 = fmaxf(mx1, fmaxf(s[nb].z, s[nb].w));
        }
        mx0 = fmaxf(mx0, __shfl_xor_sync(0xffffffffu, mx0, 1));
        mx0 = fmaxf(mx0, __shfl_xor_sync(0xffffffffu, mx0, 2));
        mx1 = fmaxf(mx1, __shfl_xor_sync(0xffffffffu, mx1, 1));
        mx1 = fmaxf(mx1, __shfl_xor_sync(0xffffffffu, mx1, 2));
        float mn0 = fmaxf(m0r, mx0), mn1 = fmaxf(m1r, mx1);
        float a0 = __expf(m0r - mn0), a1 = __expf(m1r - mn1);
        m0r = mn0; m1r = mn1;

        float rs0 = 0.f, rs1 = 0.f;
#pragma unroll
        for (int nb = 0; nb < 8; nb++) {
            float p0 = __expf(s[nb].x - mn0);
            float p1 = __expf(s[nb].y - mn0);
            float p2 = __expf(s[nb].z - mn1);
            float p3 = __expf(s[nb].w - mn1);
            rs0 += p0 + p1;
            rs1 += p2 + p3;
            uint32_t h, l;
            bsplit2(p0, p1, h, l);
            Ph[(wm + g) * FPAD + nb * 4 + q] = h;
            Pl[(wm + g) * FPAD + nb * 4 + q] = l;
            bsplit2(p2, p3, h, l);
            Ph[(wm + g + 8) * FPAD + nb * 4 + q] = h;
            Pl[(wm + g + 8) * FPAD + nb * 4 + q] = l;
        }
        rs0 += __shfl_xor_sync(0xffffffffu, rs0, 1);
        rs0 += __shfl_xor_sync(0xffffffffu, rs0, 2);
        rs1 += __shfl_xor_sync(0xffffffffu, rs1, 1);
        rs1 += __shfl_xor_sync(0xffffffffu, rs1, 2);
        l0r = l0r * a0 + rs0;
        l1r = l1r * a1 + rs1;
#pragma unroll
        for (int nb = 0; nb < 8; nb++) {
            o[nb].x *= a0; o[nb].y *= a0;
            o[nb].z *= a1; o[nb].w *= a1;
        }
        __syncwarp();

        // O += P V
#pragma unroll
        for (int ks = 0; ks < 4; ks++) {
            const int kb = ks * 8 + q;
            uint32_t ph0 = Ph[(wm + g) * FPAD + kb];
            uint32_t ph1 = Ph[(wm + g + 8) * FPAD + kb];
            uint32_t ph2 = Ph[(wm + g) * FPAD + kb + 4];
            uint32_t ph3 = Ph[(wm + g + 8) * FPAD + kb + 4];
            uint32_t pl0 = Pl[(wm + g) * FPAD + kb];
            uint32_t pl1 = Pl[(wm + g + 8) * FPAD + kb];
            uint32_t pl2 = Pl[(wm + g) * FPAD + kb + 4];
            uint32_t pl3 = Pl[(wm + g + 8) * FPAD + kb + 4];
#pragma unroll
            for (int nb = 0; nb < 8; nb++) {
                const int n = nb * 8 + g;
                uint32_t vh0 = Vth[n * FPAD + kb];
                uint32_t vh1 = Vth[n * FPAD + kb + 4];
                uint32_t vl0 = Vtl[n * FPAD + kb];
                uint32_t vl1 = Vtl[n * FPAD + kb + 4];
                mma_bf16(o[nb], ph0, ph1, ph2, ph3, vh0, vh1);
                mma_bf16(o[nb], ph0, ph1, ph2, ph3, vl0, vl1);
                mma_bf16(o[nb], pl0, pl1, pl2, pl3, vh0, vh1);
            }
        }
        buf ^= 1;
    }

    const size_t row0 = (size_t)b * Tt + q0 + wm + g;
    float* po = g_po[part];
#pragma unroll
    for (int nb = 0; nb < 8; nb++) {
        int col = nb * 8 + 2 * q;
        *(float2*)(po + row0 * HD + col)       = make_float2(o[nb].x, o[nb].y);
        *(float2*)(po + (row0 + 8) * HD + col) = make_float2(o[nb].z, o[nb].w);
    }
    if (q == 0) {
        g_pm[part][row0] = m0r;     g_pl[part][row0] = l0r;
        g_pm[part][row0 + 8] = m1r; g_pl[part][row0 + 8] = l1r;
    }
}

// ---------------------------------------------------------------------------
// Kernel 3: combine 4 split-KV partials -> pre-split bf16 HO
// ---------------------------------------------------------------------------
__global__ void combine_kernel() {
    int idx = blockIdx.x * 256 + threadIdx.x;
    int row = idx >> 5;
    int d2 = idx & 31;
    float mx = -1e30f;
#pragma unroll
    for (int p = 0; p < NSPLIT; p++) mx = fmaxf(mx, g_pm[p][row]);
    float wgt[NSPLIT];
    float l = 0.f;
#pragma unroll
    for (int p = 0; p < NSPLIT; p++) {
        wgt[p] = __expf(g_pm[p][row] - mx);
        l += g_pl[p][row] * wgt[p];
    }
    float inv = 1.f / l;
    float o0 = 0.f, o1 = 0.f;
#pragma unroll
    for (int p = 0; p < NSPLIT; p++) {
        float2 a = *(const float2*)(g_po[p] + (size_t)row * HD + 2 * d2);
        o0 += a.x * wgt[p];
        o1 += a.y * wgt[p];
    }
    o0 *= inv; o1 *= inv;
    uint32_t h, lo; bsplit2(o0, o1, h, lo);
    g_hoh[idx] = h; g_hol[idx] = lo;
}

// ---------------------------------------------------------------------------
// Kernel 4: out-proj 3xBF16. CTA 128x256, block 512 (16 warps: 8m x 2n).
// grid (64, 4) = 256 CTAs -> single wave at 2 CTAs/SM.
// ---------------------------------------------------------------------------
#define OUTP_SMEM ((2*128*FPAD + 2*256*FPAD) * 4)

__global__ void __launch_bounds__(512) outproj_mma(float* __restrict__ out) {
    extern __shared__ uint32_t smu[];
    uint32_t* Ah = smu;
    uint32_t* Al = Ah + 128 * FPAD;
    uint32_t* Bh = Al + 128 * FPAD;
    uint32_t* Bl = Bh + 256 * FPAD;

    const int m0 = blockIdx.x * 128, n0 = blockIdx.y * 256;
    const int tid = threadIdx.x;
    const int lane = tid & 31;
    const int w = tid >> 5;
    const int wm = (w & 7) * 16;
    const int ncb = (w >> 3) * 128;
    const int g = lane >> 2, q = lane & 3;

#pragma unroll
    for (int i = 0; i < 2; i++) {
        int j = tid + i * 512;
        int row = j >> 3, c = j & 7;
        *(uint4*)(Ah + row * FPAD + c * 4) = *(const uint4*)(g_hoh + (size_t)(m0 + row) * 32 + c * 4);
        *(uint4*)(Al + row * FPAD + c * 4) = *(const uint4*)(g_hol + (size_t)(m0 + row) * 32 + c * 4);
    }
#pragma unroll
    for (int i = 0; i < 4; i++) {
        int j = tid + i * 512;
        int row = j >> 3, c = j & 7;
        *(uint4*)(Bh + row * FPAD + c * 4) = *(const uint4*)(g_wrh + (size_t)(n0 + row) * 32 + c * 4);
        *(uint4*)(Bl + row * FPAD + c * 4) = *(const uint4*)(g_wrl + (size_t)(n0 + row) * 32 + c * 4);
    }
    __syncthreads();

    float4 acc[16];
#pragma unroll
    for (int nb = 0; nb < 16; nb++) acc[nb] = make_float4(0.f, 0.f, 0.f, 0.f);

#pragma unroll
    for (int ks = 0; ks < 4; ks++) {
        const int kb = ks * 8 + q;
        uint32_t ah0 = Ah[(wm + g) * FPAD + kb];
        uint32_t ah1 = Ah[(wm + g + 8) * FPAD + kb];
        uint32_t ah2 = Ah[(wm + g) * FPAD + kb + 4];
        uint32_t ah3 = Ah[(wm + g + 8) * FPAD + kb + 4];
        uint32_t al0 = Al[(wm + g) * FPAD + kb];
        uint32_t al1 = Al[(wm + g + 8) * FPAD + kb];
        uint32_t al2 = Al[(wm + g) * FPAD + kb + 4];
        uint32_t al3 = Al[(wm + g + 8) * FPAD + kb + 4];
#pragma unroll
        for (int nb = 0; nb < 16; nb++) {
            const int n = ncb + nb * 8 + g;
            uint32_t bh0 = Bh[n * FPAD + kb];
            uint32_t bh1 = Bh[n * FPAD + kb + 4];
            uint32_t bl0 = Bl[n * FPAD + kb];
            uint32_t bl1 = Bl[n * FPAD + kb + 4];
            mma_bf16(acc[nb], ah0, ah1, ah2, ah3, bh0, bh1);
            mma_bf16(acc[nb], ah0, ah1, ah2, ah3, bl0, bl1);
            mma_bf16(acc[nb], al0, al1, al2, al3, bh0, bh1);
        }
    }

    const int row0 = m0 + wm + g;
#pragma unroll
    for (int nb = 0; nb < 16; nb++) {
        int col = n0 + ncb + nb * 8 + 2 * q;
        *(float2*)(out + (size_t)row0 * 1024 + col)       = make_float2(acc[nb].x, acc[nb].y);
        *(float2*)(out + (size_t)(row0 + 8) * 1024 + col) = make_float2(acc[nb].z, acc[nb].w);
    }
}

// ---------------------------------------------------------------------------
extern "C" void kernel_launch(void* const* d_in, const int* in_sizes, int n_in,
                              void* d_out, int out_size) {
    (void)in_sizes; (void)n_in; (void)out_size;
    const float* emb  = (const float*)d_in[0];
    const float* Wq   = (const float*)d_in[1];
    const float* Wk   = (const float*)d_in[2];
    const float* Wv   = (const float*)d_in[3];
    const float* Wout = (const float*)d_in[4];
    float* out = (float*)d_out;

    prep_kernel<<<512, 256>>>(Wq, Wk, Wv, Wout);

    cudaFuncSetAttribute(qkv_fused, cudaFuncAttributeMaxDynamicSharedMemorySize, QKV_SMEM);
    qkv_fused<<<128, 512, QKV_SMEM>>>(emb);

    vsplit_kernel<<<Mrows * 32 / 256, 256>>>();

    cudaFuncSetAttribute(flash_mma, cudaFuncAttributeMaxDynamicSharedMemorySize, FL_SMEM);
    flash_mma<<<dim3(64, 4), 256, FL_SMEM>>>();

    combine_kernel<<<Mrows * 32 / 256, 256>>>();

    cudaFuncSetAttribute(outproj_mma, cudaFuncAttributeMaxDynamicSharedMemorySize, OUTP_SMEM);
    outproj_mma<<<dim3(64, 4), 512, OUTP_SMEM>>>(out);
}